// round 12
// baseline (speedup 1.0000x reference)
#include <cuda_runtime.h>
#include <cuda_bf16.h>
#include <cstdint>
#include <math.h>

#define BN    8
#define CINC  256
#define CMID  128
#define COUTC 256
#define HH    128
#define WW    128
#define HWSZ  16384

typedef uint32_t u32;

// ---------------- scratch (static __device__ — allocation-free) ----------------
__device__ float g_y[4][BN * CMID * HH * WW];  // branch conv outputs (post-relu)
__device__ float g_S[BN * CMID * HH * WW];     // sum of 4 scanned branches
// bf16-split weights: branch [tap=br*9+kh*3+kw][co=128][cipair=128]
__device__ __align__(16) __nv_bfloat162 g_wAh[36 * 128 * 128];
__device__ __align__(16) __nv_bfloat162 g_wAl[36 * 128 * 128];
__device__ __align__(16) __nv_bfloat162 g_w2h[9 * 256 * 64];   // [t][co=256][cipair=64]
__device__ __align__(16) __nv_bfloat162 g_w2l[9 * 256 * 64];
__device__ __align__(16) __nv_bfloat162 g_w1h[256 * 128];      // [co=256][cipair=128]
__device__ __align__(16) __nv_bfloat162 g_w1l[256 * 128];

// ---------------- helpers ----------------
__device__ __forceinline__ u32 smem_u32(const void* p) {
    u32 a;
    asm("{ .reg .u64 t; cvta.to.shared.u64 t, %1; cvt.u32.u64 %0, t; }" : "=r"(a) : "l"(p));
    return a;
}

// XOR swizzle: byte bits [6:4] ^= bits [9:7]  (rows are 128B)
#define SWZ(off) ((off) ^ (((off) >> 3) & 0x70))

__device__ __forceinline__ void ldm_x4(u32* r, u32 addr) {
    asm volatile("ldmatrix.sync.aligned.m8n8.x4.shared.b16 {%0,%1,%2,%3}, [%4];"
                 : "=r"(r[0]), "=r"(r[1]), "=r"(r[2]), "=r"(r[3]) : "r"(addr));
}
__device__ __forceinline__ void mma16816(float* d, const u32* a, const u32* b) {
    asm volatile("mma.sync.aligned.m16n8k16.row.col.f32.bf16.bf16.f32 "
                 "{%0,%1,%2,%3}, {%4,%5,%6,%7}, {%8,%9}, {%0,%1,%2,%3};"
                 : "+f"(d[0]), "+f"(d[1]), "+f"(d[2]), "+f"(d[3])
                 : "r"(a[0]), "r"(a[1]), "r"(a[2]), "r"(a[3]), "r"(b[0]), "r"(b[1]));
}
__device__ __forceinline__ void cpa16(u32 d, const void* s) {
    asm volatile("cp.async.cg.shared.global [%0], [%1], 16;" :: "r"(d), "l"(s));
}
#define CPA_COMMIT() asm volatile("cp.async.commit_group;" ::: "memory")
#define CPA_WAIT0()  asm volatile("cp.async.wait_group 0;" ::: "memory")
#define PAIR_BAR(id) asm volatile("bar.sync %0, 64;" :: "r"(id) : "memory")

// smem: two A buffers (256 rows: hi 32KB + lo 32KB), two B buffers (132 rows, hi+lo)
#define BSZ    16896                    // 132 * 128 bytes
#define ASZ    32768                    // 256 * 128 bytes (one half)
#define OFF_A0 0
#define OFF_A1 65536
#define OFF_B0 131072
#define OFF_B1 (131072 + 2 * BSZ)       // 164864
#define SMEM_BYTES (OFF_B1 + 2 * BSZ)   // 198656

__device__ __forceinline__ void split2(float v0, float v1, u32 sb, u32 offB, u32 off) {
    __nv_bfloat16 h0 = __float2bfloat16(v0), h1 = __float2bfloat16(v1);
    __nv_bfloat16 l0 = __float2bfloat16(v0 - __bfloat162float(h0));
    __nv_bfloat16 l1 = __float2bfloat16(v1 - __bfloat162float(h1));
    u32 sw = SWZ(off);
    u32 hv, lv;
    asm("mov.b32 %0, {%1, %2};" : "=r"(hv) : "h"(*(unsigned short*)&h0), "h"(*(unsigned short*)&h1));
    asm("mov.b32 %0, {%1, %2};" : "=r"(lv) : "h"(*(unsigned short*)&l0), "h"(*(unsigned short*)&l1));
    asm volatile("st.shared.b32 [%0], %1;" :: "r"(sb + offB + sw), "r"(hv) : "memory");
    asm volatile("st.shared.b32 [%0], %1;" :: "r"(sb + offB + BSZ + sw), "r"(lv) : "memory");
}

// ---------------- weight repack (+BN scale fold, bf16 hi/lo split) ----------------
__global__ void k_repack_br(const float* __restrict__ w, const float* __restrict__ s, int br)
{
    int slot = blockIdx.x * 256 + threadIdx.x;       // 9*128*128
    if (slot >= 147456) return;
    int pair = slot & 127;
    int co   = (slot >> 7) & 127;
    int t    = slot >> 14;
    int kh = t / 3, kw = t % 3;
    int ci = pair * 2;
    float sc = s[co];
    float v0 = w[((co * CINC + ci)     * 3 + kh) * 3 + kw] * sc;
    float v1 = w[((co * CINC + ci + 1) * 3 + kh) * 3 + kw] * sc;
    __nv_bfloat16 h0 = __float2bfloat16(v0), h1 = __float2bfloat16(v1);
    __nv_bfloat16 l0 = __float2bfloat16(v0 - __bfloat162float(h0));
    __nv_bfloat16 l1 = __float2bfloat16(v1 - __bfloat162float(h1));
    int idx = ((br * 9 + t) * 128 + co) * 128 + pair;
    g_wAh[idx] = __halves2bfloat162(h0, h1);
    g_wAl[idx] = __halves2bfloat162(l0, l1);
}

__global__ void k_repack_w2(const float* __restrict__ w, const float* __restrict__ s)
{
    int slot = blockIdx.x * 256 + threadIdx.x;       // 9*256*64
    if (slot >= 147456) return;
    int pair = slot & 63;
    int co   = (slot >> 6) & 255;
    int t    = slot >> 14;
    int kh = t / 3, kw = t % 3;
    int ci = pair * 2;
    float sc = s[co];
    float v0 = w[((co * CMID + ci)     * 3 + kh) * 3 + kw] * sc;
    float v1 = w[((co * CMID + ci + 1) * 3 + kh) * 3 + kw] * sc;
    __nv_bfloat16 h0 = __float2bfloat16(v0), h1 = __float2bfloat16(v1);
    __nv_bfloat16 l0 = __float2bfloat16(v0 - __bfloat162float(h0));
    __nv_bfloat16 l1 = __float2bfloat16(v1 - __bfloat162float(h1));
    int idx = (t * 256 + co) * 64 + pair;
    g_w2h[idx] = __halves2bfloat162(h0, h1);
    g_w2l[idx] = __halves2bfloat162(l0, l1);
}

__global__ void k_repack_w1(const float* __restrict__ w, const float* __restrict__ s)
{
    int slot = blockIdx.x * 256 + threadIdx.x;       // 256*128
    if (slot >= 32768) return;
    int pair = slot & 127;
    int co   = slot >> 7;
    int ci = pair * 2;
    float sc = s[co];
    float v0 = w[co * CINC + ci]     * sc;
    float v1 = w[co * CINC + ci + 1] * sc;
    __nv_bfloat16 h0 = __float2bfloat16(v0), h1 = __float2bfloat16(v1);
    __nv_bfloat16 l0 = __float2bfloat16(v0 - __bfloat162float(h0));
    __nv_bfloat16 l1 = __float2bfloat16(v1 - __bfloat162float(h1));
    g_w1h[co * 128 + pair] = __halves2bfloat162(h0, h1);
    g_w1l[co * 128 + pair] = __halves2bfloat162(l0, l1);
}

// ---------------- per-warp A copy: 32 rows x 128B of ONE plane (hi or lo) ----------------
// wn=0 copies hi plane (offA), wn=1 copies lo plane (offA+ASZ); caller picks wsrc to match.
__device__ __forceinline__ void build_A_warp(u32 sb, u32 offA, int wm, int wn, int lane,
                                             const __nv_bfloat162* __restrict__ wsrc,
                                             int rsp, int pair0, size_t hi_off)
{
    u32 dbase = sb + offA + (wn ? ASZ : 0);
#pragma unroll
    for (int q = 0; q < 8; q++) {
        int slot = lane + 32 * q;            // 0..255
        int co = wm * 32 + (slot >> 3);
        int c  = slot & 7;
        u32 d = SWZ((u32)(co * 128 + c * 16));
        size_t idx = (co < 128 ? (size_t)co * rsp : hi_off + (size_t)(co - 128) * rsp) + pair0;
        cpa16(dbase + d, (const char*)(wsrc + idx) + c * 16);
    }
}

// ---------------- B staged through registers ----------------
struct BReg { float m[16]; float t0, t1; };

__device__ __forceinline__ void ldg_B(BReg& r, int tid, const float* __restrict__ src,
                                      int nchan, int b, int c0, int srow)
{
    const size_t HW = (size_t)HWSZ;
    bool rowok = (srow >= 0) && (srow < HH);
    const float* base = src + ((size_t)(b * nchan + c0) * HH + (rowok ? srow : 0)) * WW;
    int p  = tid & 127;
    int gp = tid >> 7;
    int spx = p - 1;
    bool okm = rowok && (spx >= 0);
    const float* bp = base + spx;
#pragma unroll
    for (int q = 0; q < 8; q++) {
        int cil = gp * 16 + 2 * q;
        r.m[2 * q]     = okm ? bp[(size_t)cil * HW] : 0.f;
        r.m[2 * q + 1] = okm ? bp[(size_t)(cil + 1) * HW] : 0.f;
    }
    if (tid < 128) {
        int rr = 128 + (tid >> 5);
        int pc = tid & 31;
        int cil = 2 * pc;
        int sp2 = rr - 1;
        bool ok = rowok && (sp2 < WW);
        r.t0 = ok ? base[(size_t)cil * HW + sp2] : 0.f;
        r.t1 = ok ? base[(size_t)(cil + 1) * HW + sp2] : 0.f;
    }
}

__device__ __forceinline__ void st_B(const BReg& r, u32 sb, u32 offB, int tid)
{
    int p  = tid & 127;
    int gp = tid >> 7;
#pragma unroll
    for (int q = 0; q < 8; q++) {
        int cil = gp * 16 + 2 * q;
        split2(r.m[2 * q], r.m[2 * q + 1], sb, offB, (u32)(p * 128 + 2 * cil));
    }
    if (tid < 128) {
        int rr = 128 + (tid >> 5);
        int pc = tid & 31;
        split2(r.t0, r.t1, sb, offB, (u32)(rr * 128 + 4 * pc));
    }
}

// ---------------- mma over one 64-k chunk; M=256, warp = 32co x 64px ----------------
// 16 warps: wm = wid>>1 (0..7), wn = wid&1 (0..1)
__device__ __forceinline__ void mma_chunk(u32 sb, u32 offA, u32 offB, int kw,
                                          int wm, int wn, int lid, float acc[2][8][4])
{
    const u32 lrow  = (u32)(lid & 15) * 128;
    const u32 lkh   = (u32)((lid >> 4) << 4);
    const u32 brow0 = (u32)kw * 128 + lrow;
#pragma unroll
    for (int ks = 0; ks < 4; ks++) {
        const u32 kb = (u32)(ks * 32) + lkh;
        u32 ah[2][4], al[2][4], bh[4][4], bl[4][4];
#pragma unroll
        for (int mt = 0; mt < 2; mt++) {
            u32 off = SWZ((u32)((wm * 32 + mt * 16) * 128) + lrow + kb);
            ldm_x4(ah[mt], sb + offA + off);
            ldm_x4(al[mt], sb + offA + ASZ + off);
        }
#pragma unroll
        for (int bt = 0; bt < 4; bt++) {
            u32 off = SWZ((u32)((wn * 64 + bt * 16) * 128) + brow0 + kb);
            ldm_x4(bh[bt], sb + offB + off);
            ldm_x4(bl[bt], sb + offB + BSZ + off);
        }
#pragma unroll
        for (int mt = 0; mt < 2; mt++)
#pragma unroll
            for (int bt = 0; bt < 4; bt++)
#pragma unroll
                for (int j = 0; j < 2; j++) {
                    u32 BH2[2] = { bh[bt][j], bh[bt][j + 2] };
                    u32 BL2[2] = { bl[bt][j], bl[bt][j + 2] };
                    float* d = acc[mt][bt * 2 + j];
                    mma16816(d, ah[mt], BH2);
                    mma16816(d, ah[mt], BL2);
                    mma16816(d, al[mt], BH2);
                }
    }
}

// ---------------- fused branch-PAIR 3x3 conv + BN + relu ----------------
// grid = (H=128, B=8, pair=2); per-warp-pair A pipeline, 1 CTA sync per chunk.
__global__ __launch_bounds__(512, 1)
void k_conv_branch(const float* __restrict__ x,
                   const float* __restrict__ ob0, const float* __restrict__ ob1,
                   const float* __restrict__ ob2, const float* __restrict__ ob3)
{
    extern __shared__ char smem_raw[];
    u32 sb = smem_u32(smem_raw);
    const int h  = blockIdx.x;
    const int b  = blockIdx.y;
    const int bz = blockIdx.z;
    const int tid = threadIdx.x;
    const int wid = tid >> 5, lid = tid & 31;
    const int wm = wid >> 1, wn = wid & 1;
    const size_t HIOFF = 9 * 16384;                  // +1 branch in g_wA
    const __nv_bfloat162* wbase = wn ? g_wAl : g_wAh;

    float acc[2][8][4];
#pragma unroll
    for (int i = 0; i < 2; i++)
#pragma unroll
        for (int j = 0; j < 8; j++)
#pragma unroll
            for (int k = 0; k < 4; k++) acc[i][j][k] = 0.f;

    BReg breg;
    ldg_B(breg, tid, x, CINC, b, 0, h - 1);          // chunk 0: kh=0, c0=0
    {   // step 0 A copy (own plane, own rows)
        size_t t0 = (size_t)(bz * 18) * 16384;
        build_A_warp(sb, OFF_A0, wm, wn, lid, wbase + t0, 128, 0, HIOFF);
        CPA_COMMIT();
    }

    for (int ch = 0; ch < 12; ch++) {
        u32 offB = (ch & 1) ? OFF_B1 : OFF_B0;
        st_B(breg, sb, offB, tid);
        __syncthreads();                             // only CTA-wide sync per chunk
        if (ch + 1 < 12) {
            int kh2 = (ch + 1) >> 2, c02 = ((ch + 1) & 3) * 64;
            ldg_B(breg, tid, x, CINC, b, c02, h + kh2 - 1);    // drains under MMAs
        }
#pragma unroll
        for (int kw = 0; kw < 3; kw++) {
            int step = ch * 3 + kw;
            CPA_WAIT0();                             // own copies of tap `step`
            PAIR_BAR(1 + wm);                        // partner's plane visible; buffer freed
            if (step + 1 < 36) {
                int s2 = step + 1, ch2 = s2 / 3, kw2 = s2 - ch2 * 3;
                int kh2 = ch2 >> 2, c02 = (ch2 & 3) * 64;
                size_t tn = (size_t)(bz * 18 + kh2 * 3 + kw2) * 16384;
                build_A_warp(sb, (s2 & 1) ? OFF_A1 : OFF_A0, wm, wn, lid,
                             wbase + tn, 128, c02 >> 1, HIOFF);
                CPA_COMMIT();
            }
            mma_chunk(sb, (step & 1) ? OFF_A1 : OFF_A0, offB, kw, wm, wn, lid, acc);
        }
    }

    const float* obs[4] = { ob0, ob1, ob2, ob3 };
#pragma unroll
    for (int mt = 0; mt < 2; mt++) {
        int r0 = wm * 32 + mt * 16 + (lid >> 2);     // 0..255
#pragma unroll
        for (int half = 0; half < 2; half++) {
            int co  = r0 + half * 8;
            int brl = co >> 7;
            int cob = co & 127;
            float sh = obs[2 * bz + brl][cob];
            float* row = g_y[2 * bz + brl] + ((size_t)(b * CMID + cob) * HH + h) * WW;
#pragma unroll
            for (int nf = 0; nf < 8; nf++) {
                int px = wn * 64 + nf * 8 + 2 * (lid & 3);
                float2 v;
                v.x = fmaxf(acc[mt][nf][half * 2 + 0] + sh, 0.f);
                v.y = fmaxf(acc[mt][nf][half * 2 + 1] + sh, 0.f);
                *(float2*)(row + px) = v;
            }
        }
    }
}

// ---------------- scans along W (warp-per-row, float4 + shfl scan) ----------------
__global__ void k_scan_w()
{
    int bc   = blockIdx.x;
    int wq   = threadIdx.x >> 5;
    int lane = threadIdx.x & 31;
    const size_t plane = (size_t)bc * HH * WW;
    for (int hr = wq; hr < HH; hr += 16) {
        const float4* yl4 = (const float4*)(g_y[0] + plane + (size_t)hr * WW);
        const float4* yr4 = (const float4*)(g_y[1] + plane + (size_t)hr * WW);
        float4 a = yl4[lane];
        float4 r = yr4[lane];
        float p0 = r.x, p1 = fmaxf(p0, r.y), p2 = fmaxf(p1, r.z), p3 = fmaxf(p2, r.w);
        float m = p3;
#pragma unroll
        for (int o = 1; o < 32; o <<= 1) {
            float v = __shfl_up_sync(0xffffffffu, m, o);
            if (lane >= o) m = fmaxf(m, v);
        }
        float ex = __shfl_up_sync(0xffffffffu, m, 1);
        if (lane == 0) ex = -INFINITY;
        float q3 = a.w, q2 = fmaxf(q3, a.z), q1 = fmaxf(q2, a.y), q0 = fmaxf(q1, a.x);
        float mm = q0;
#pragma unroll
        for (int o = 1; o < 32; o <<= 1) {
            float v = __shfl_down_sync(0xffffffffu, mm, o);
            if (lane + o < 32) mm = fmaxf(mm, v);
        }
        float exr = __shfl_down_sync(0xffffffffu, mm, 1);
        if (lane == 31) exr = -INFINITY;
        float4 o4;
        o4.x = fmaxf(ex, p0) + fmaxf(exr, q0);
        o4.y = fmaxf(ex, p1) + fmaxf(exr, q1);
        o4.z = fmaxf(ex, p2) + fmaxf(exr, q2);
        o4.w = fmaxf(ex, p3) + fmaxf(exr, q3);
        ((float4*)(g_S + plane + (size_t)hr * WW))[lane] = o4;
    }
}

// ---------------- scans along H (coalesced columns) ----------------
__global__ void k_scan_h()
{
    int bc = blockIdx.x;
    int w  = threadIdx.x;
    const float* yt = g_y[2] + (size_t)bc * (HH * WW) + w;
    const float* yv = g_y[3] + (size_t)bc * (HH * WW) + w;
    float* Sp = g_S + (size_t)bc * (HH * WW) + w;
    float m = -INFINITY;
    for (int hq = HH - 1; hq >= 0; --hq) { m = fmaxf(m, yt[hq * WW]); Sp[hq * WW] += m; }
    m = -INFINITY;
    for (int hq = 0; hq < HH; ++hq)      { m = fmaxf(m, yv[hq * WW]); Sp[hq * WW] += m; }
}

// ---------------- conv2 3x3 over S + 1x1 skip over x + relu -> out ----------------
// grid = (H=128, B=8, 1), 512 threads, M=256, per-warp-pair A pipeline
__device__ __forceinline__ void prefetch_A_out_warp(u32 sb, int wm, int wn, int lane, int s)
{
    u32 offA = (s & 1) ? OFF_A1 : OFF_A0;
    if (s < 18) {
        int ch = s / 3, kw = s - ch * 3;
        int kh = ch >> 1, c0 = (ch & 1) * 64;
        size_t tn = (size_t)(kh * 3 + kw) * 256 * 64;
        build_A_warp(sb, offA, wm, wn, lane,
                     (wn ? g_w2l : g_w2h) + tn, 64, c0 >> 1, (size_t)128 * 64);
    } else {
        int c = s - 18;
        build_A_warp(sb, offA, wm, wn, lane,
                     (wn ? g_w1l : g_w1h), 128, c * 32, (size_t)128 * 128);
    }
    CPA_COMMIT();
}

__global__ __launch_bounds__(512, 1)
void k_conv_out(const float* __restrict__ x,
                const float* __restrict__ o2v, const float* __restrict__ o1v,
                float* __restrict__ out)
{
    extern __shared__ char smem_raw[];
    u32 sb = smem_u32(smem_raw);
    const int h  = blockIdx.x;
    const int b  = blockIdx.y;
    const int tid = threadIdx.x;
    const int wid = tid >> 5, lid = tid & 31;
    const int wm = wid >> 1, wn = wid & 1;

    float acc[2][8][4];
#pragma unroll
    for (int i = 0; i < 2; i++)
#pragma unroll
        for (int j = 0; j < 8; j++)
#pragma unroll
            for (int k = 0; k < 4; k++) acc[i][j][k] = 0.f;

    BReg breg;
    ldg_B(breg, tid, g_S, CMID, b, 0, h - 1);        // phase1 chunk 0
    prefetch_A_out_warp(sb, wm, wn, lid, 0);

    // phase 1: 3x3 conv over g_S (6 chunks x 3 kw = 18 steps)
    for (int ch = 0; ch < 6; ch++) {
        u32 offB = (ch & 1) ? OFF_B1 : OFF_B0;
        st_B(breg, sb, offB, tid);
        __syncthreads();
        if (ch + 1 < 6) {
            int kh2 = (ch + 1) >> 1, c02 = ((ch + 1) & 1) * 64;
            ldg_B(breg, tid, g_S, CMID, b, c02, h + kh2 - 1);
        } else {
            ldg_B(breg, tid, x, CINC, b, 0, h);      // bridge to phase 2
        }
#pragma unroll
        for (int kw = 0; kw < 3; kw++) {
            int step = ch * 3 + kw;
            CPA_WAIT0();
            PAIR_BAR(1 + wm);
            if (step + 1 < 22) prefetch_A_out_warp(sb, wm, wn, lid, step + 1);
            mma_chunk(sb, (step & 1) ? OFF_A1 : OFF_A0, offB, kw, wm, wn, lid, acc);
        }
    }
    // phase 2: 1x1 skip over x (4 chunks, 1 step each; brow offset 1 = unshifted)
    for (int c = 0; c < 4; c++) {
        int ch = 6 + c;
        u32 offB = (ch & 1) ? OFF_B1 : OFF_B0;
        st_B(breg, sb, offB, tid);
        __syncthreads();
        if (c + 1 < 4) ldg_B(breg, tid, x, CINC, b, (c + 1) * 64, h);
        int step = 18 + c;
        CPA_WAIT0();
        PAIR_BAR(1 + wm);
        if (step + 1 < 22) prefetch_A_out_warp(sb, wm, wn, lid, step + 1);
        mma_chunk(sb, (step & 1) ? OFF_A1 : OFF_A0, offB, 1, wm, wn, lid, acc);
    }

#pragma unroll
    for (int mt = 0; mt < 2; mt++) {
        int r0 = wm * 32 + mt * 16 + (lid >> 2);
#pragma unroll
        for (int half = 0; half < 2; half++) {
            int co = r0 + half * 8;                  // 0..255
            float sh = o2v[co] + o1v[co];
            float* row = out + ((size_t)(b * COUTC + co) * HH + h) * WW;
#pragma unroll
            for (int nf = 0; nf < 8; nf++) {
                int px = wn * 64 + nf * 8 + 2 * (lid & 3);
                float2 v;
                v.x = fmaxf(acc[mt][nf][half * 2 + 0] + sh, 0.f);
                v.y = fmaxf(acc[mt][nf][half * 2 + 1] + sh, 0.f);
                *(float2*)(row + px) = v;
            }
        }
    }
}

// ---------------- launch ----------------
// NOTE: launch order puts k_conv_branch at index 5 so ncu (-s 5 -c 1) captures it.
extern "C" void kernel_launch(void* const* d_in, const int* in_sizes, int n_in,
                              void* d_out, int out_size)
{
    const float* x   = (const float*)d_in[0];
    const float* w_l = (const float*)d_in[1];
    const float* s_l = (const float*)d_in[2];
    const float* o_l = (const float*)d_in[3];
    const float* w_r = (const float*)d_in[4];
    const float* s_r = (const float*)d_in[5];
    const float* o_r = (const float*)d_in[6];
    const float* w_t = (const float*)d_in[7];
    const float* s_t = (const float*)d_in[8];
    const float* o_t = (const float*)d_in[9];
    const float* w_b = (const float*)d_in[10];
    const float* s_b = (const float*)d_in[11];
    const float* o_b = (const float*)d_in[12];
    const float* w2  = (const float*)d_in[13];
    const float* s2  = (const float*)d_in[14];
    const float* o2  = (const float*)d_in[15];
    const float* w1  = (const float*)d_in[16];
    const float* s1  = (const float*)d_in[17];
    const float* o1  = (const float*)d_in[18];
    float* out = (float*)d_out;

    cudaFuncSetAttribute(k_conv_branch, cudaFuncAttributeMaxDynamicSharedMemorySize, SMEM_BYTES);
    cudaFuncSetAttribute(k_conv_out,    cudaFuncAttributeMaxDynamicSharedMemorySize, SMEM_BYTES);

    k_repack_br<<<576, 256>>>(w_l, s_l, 0);          // 0
    k_repack_br<<<576, 256>>>(w_r, s_r, 1);          // 1
    k_repack_br<<<576, 256>>>(w_t, s_t, 2);          // 2
    k_repack_br<<<576, 256>>>(w_b, s_b, 3);          // 3
    k_repack_w2<<<576, 256>>>(w2, s2);               // 4
    dim3 g1(HH, BN, 2);
    k_conv_branch<<<g1, 512, SMEM_BYTES>>>(x, o_l, o_r, o_t, o_b);   // 5 <- ncu target
    k_repack_w1<<<128, 256>>>(w1, s1);               // 6 (needed only by conv_out)
    k_scan_w<<<BN * CMID, 512>>>();
    k_scan_h<<<BN * CMID, 128>>>();
    dim3 g3(HH, BN, 1);
    k_conv_out<<<g3, 512, SMEM_BYTES>>>(x, o2, o1, out);
}

// round 13
// speedup vs baseline: 1.3717x; 1.3717x over previous
#include <cuda_runtime.h>
#include <cuda_fp16.h>
#include <cstdint>
#include <math.h>

#define BN    8
#define CINC  256
#define CMID  128
#define COUTC 256
#define HH    128
#define WW    128
#define HWSZ  16384

typedef uint32_t u32;

// ---------------- scratch (static __device__ — allocation-free) ----------------
__device__ float g_y[4][BN * CMID * HH * WW];  // branch conv outputs (post-relu)
__device__ float g_S[BN * CMID * HH * WW];     // sum of 4 scanned branches
// fp16-split weights (hi+lo planes): branch [tap=br*9+kh*3+kw][co=128][cipair=128]
__device__ __align__(16) __half2 g_wAh[36 * 128 * 128];
__device__ __align__(16) __half2 g_wAl[36 * 128 * 128];
__device__ __align__(16) __half2 g_w2h[9 * 256 * 64];   // [t][co=256][cipair=64]
__device__ __align__(16) __half2 g_w2l[9 * 256 * 64];
__device__ __align__(16) __half2 g_w1h[256 * 128];      // [co=256][cipair=128]
__device__ __align__(16) __half2 g_w1l[256 * 128];

// ---------------- helpers ----------------
__device__ __forceinline__ u32 smem_u32(const void* p) {
    u32 a;
    asm("{ .reg .u64 t; cvta.to.shared.u64 t, %1; cvt.u32.u64 %0, t; }" : "=r"(a) : "l"(p));
    return a;
}

// XOR swizzle: byte bits [6:4] ^= bits [9:7]  (rows are 128B)
#define SWZ(off) ((off) ^ (((off) >> 3) & 0x70))

__device__ __forceinline__ void ldm_x4(u32* r, u32 addr) {
    asm volatile("ldmatrix.sync.aligned.m8n8.x4.shared.b16 {%0,%1,%2,%3}, [%4];"
                 : "=r"(r[0]), "=r"(r[1]), "=r"(r[2]), "=r"(r[3]) : "r"(addr));
}
__device__ __forceinline__ void mma16816(float* d, const u32* a, const u32* b) {
    asm volatile("mma.sync.aligned.m16n8k16.row.col.f32.f16.f16.f32 "
                 "{%0,%1,%2,%3}, {%4,%5,%6,%7}, {%8,%9}, {%0,%1,%2,%3};"
                 : "+f"(d[0]), "+f"(d[1]), "+f"(d[2]), "+f"(d[3])
                 : "r"(a[0]), "r"(a[1]), "r"(a[2]), "r"(a[3]), "r"(b[0]), "r"(b[1]));
}
__device__ __forceinline__ void cpa16(u32 d, const void* s) {
    asm volatile("cp.async.cg.shared.global [%0], [%1], 16;" :: "r"(d), "l"(s));
}
#define CPA_COMMIT() asm volatile("cp.async.commit_group;" ::: "memory")
#define CPA_WAIT0()  asm volatile("cp.async.wait_group 0;" ::: "memory")
#define PAIR_BAR(id) asm volatile("bar.sync %0, 64;" :: "r"(id) : "memory")

// smem: two A buffers (256 rows, hi 32KB + lo 32KB each), two single-plane B buffers
#define BSZ    16896                    // 132 * 128 bytes
#define ASZ    32768                    // 256 * 128 bytes (one plane)
#define OFF_A0 0
#define OFF_A1 65536
#define OFF_B0 131072
#define OFF_B1 (131072 + BSZ)           // 147968
#define SMEM_BYTES (OFF_B1 + BSZ)       // 164864

// pack two fp32 -> fp16x2 word and store to smem (no residual math — B is single-plane)
__device__ __forceinline__ void stpack(float v0, float v1, u32 addr) {
    __half h0 = __float2half(v0), h1 = __float2half(v1);
    u32 hv;
    asm("mov.b32 %0, {%1, %2};" : "=r"(hv) : "h"(*(unsigned short*)&h0), "h"(*(unsigned short*)&h1));
    asm volatile("st.shared.b32 [%0], %1;" :: "r"(addr), "r"(hv) : "memory");
}

// ---------------- weight repack (+BN scale fold, fp16 hi/lo split) ----------------
__global__ void k_repack_br(const float* __restrict__ w, const float* __restrict__ s, int br)
{
    int slot = blockIdx.x * 256 + threadIdx.x;       // 9*128*128
    if (slot >= 147456) return;
    int pair = slot & 127;
    int co   = (slot >> 7) & 127;
    int t    = slot >> 14;
    int kh = t / 3, kw = t % 3;
    int ci = pair * 2;
    float sc = s[co];
    float v0 = w[((co * CINC + ci)     * 3 + kh) * 3 + kw] * sc;
    float v1 = w[((co * CINC + ci + 1) * 3 + kh) * 3 + kw] * sc;
    __half h0 = __float2half(v0), h1 = __float2half(v1);
    __half l0 = __float2half(v0 - __half2float(h0));
    __half l1 = __float2half(v1 - __half2float(h1));
    int idx = ((br * 9 + t) * 128 + co) * 128 + pair;
    g_wAh[idx] = __halves2half2(h0, h1);
    g_wAl[idx] = __halves2half2(l0, l1);
}

__global__ void k_repack_w2(const float* __restrict__ w, const float* __restrict__ s)
{
    int slot = blockIdx.x * 256 + threadIdx.x;       // 9*256*64
    if (slot >= 147456) return;
    int pair = slot & 63;
    int co   = (slot >> 6) & 255;
    int t    = slot >> 14;
    int kh = t / 3, kw = t % 3;
    int ci = pair * 2;
    float sc = s[co];
    float v0 = w[((co * CMID + ci)     * 3 + kh) * 3 + kw] * sc;
    float v1 = w[((co * CMID + ci + 1) * 3 + kh) * 3 + kw] * sc;
    __half h0 = __float2half(v0), h1 = __float2half(v1);
    __half l0 = __float2half(v0 - __half2float(h0));
    __half l1 = __float2half(v1 - __half2float(h1));
    int idx = (t * 256 + co) * 64 + pair;
    g_w2h[idx] = __halves2half2(h0, h1);
    g_w2l[idx] = __halves2half2(l0, l1);
}

__global__ void k_repack_w1(const float* __restrict__ w, const float* __restrict__ s)
{
    int slot = blockIdx.x * 256 + threadIdx.x;       // 256*128
    if (slot >= 32768) return;
    int pair = slot & 127;
    int co   = slot >> 7;
    int ci = pair * 2;
    float sc = s[co];
    float v0 = w[co * CINC + ci]     * sc;
    float v1 = w[co * CINC + ci + 1] * sc;
    __half h0 = __float2half(v0), h1 = __float2half(v1);
    __half l0 = __float2half(v0 - __half2float(h0));
    __half l1 = __float2half(v1 - __half2float(h1));
    g_w1h[co * 128 + pair] = __halves2half2(h0, h1);
    g_w1l[co * 128 + pair] = __halves2half2(l0, l1);
}

// ---------------- per-warp A copy: 32 rows x 128B of ONE plane (hi or lo) ----------------
// wn=0 copies hi plane (offA), wn=1 copies lo plane (offA+ASZ); caller picks wsrc to match.
__device__ __forceinline__ void build_A_warp(u32 sb, u32 offA, int wm, int wn, int lane,
                                             const __half2* __restrict__ wsrc,
                                             int rsp, int pair0, size_t hi_off)
{
    u32 dbase = sb + offA + (wn ? ASZ : 0);
#pragma unroll
    for (int q = 0; q < 8; q++) {
        int slot = lane + 32 * q;            // 0..255
        int co = wm * 32 + (slot >> 3);
        int c  = slot & 7;
        u32 d = SWZ((u32)(co * 128 + c * 16));
        size_t idx = (co < 128 ? (size_t)co * rsp : hi_off + (size_t)(co - 128) * rsp) + pair0;
        cpa16(dbase + d, (const char*)(wsrc + idx) + c * 16);
    }
}

// ---------------- B staged through registers ----------------
struct BReg { float m[16]; float t0, t1; };

__device__ __forceinline__ void ldg_B(BReg& r, int tid, const float* __restrict__ src,
                                      int nchan, int b, int c0, int srow)
{
    const size_t HW = (size_t)HWSZ;
    bool rowok = (srow >= 0) && (srow < HH);
    const float* base = src + ((size_t)(b * nchan + c0) * HH + (rowok ? srow : 0)) * WW;
    int p  = tid & 127;
    int gp = tid >> 7;
    int spx = p - 1;
    bool okm = rowok && (spx >= 0);
    const float* bp = base + spx;
#pragma unroll
    for (int q = 0; q < 8; q++) {
        int cil = gp * 16 + 2 * q;
        r.m[2 * q]     = okm ? bp[(size_t)cil * HW] : 0.f;
        r.m[2 * q + 1] = okm ? bp[(size_t)(cil + 1) * HW] : 0.f;
    }
    if (tid < 128) {
        int rr = 128 + (tid >> 5);
        int pc = tid & 31;
        int cil = 2 * pc;
        int sp2 = rr - 1;
        bool ok = rowok && (sp2 < WW);
        r.t0 = ok ? base[(size_t)cil * HW + sp2] : 0.f;
        r.t1 = ok ? base[(size_t)(cil + 1) * HW + sp2] : 0.f;
    }
}

__device__ __forceinline__ void st_B(const BReg& r, u32 sb, u32 offB, int tid)
{
    int p  = tid & 127;
    int gp = tid >> 7;
#pragma unroll
    for (int q = 0; q < 8; q++) {
        int cil = gp * 16 + 2 * q;
        stpack(r.m[2 * q], r.m[2 * q + 1], sb + offB + SWZ((u32)(p * 128 + 2 * cil)));
    }
    if (tid < 128) {
        int rr = 128 + (tid >> 5);
        int pc = tid & 31;
        stpack(r.t0, r.t1, sb + offB + SWZ((u32)(rr * 128 + 4 * pc)));
    }
}

// ---------------- mma over one 64-k chunk; M=256, warp = 32co x 64px ----------------
// 16 warps: wm = wid>>1 (0..7), wn = wid&1 (0..1)
// 2 products: a_hi*b + a_lo*b  (activation fp16 residue dropped — see theory)
__device__ __forceinline__ void mma_chunk(u32 sb, u32 offA, u32 offB, int kw,
                                          int wm, int wn, int lid, float acc[2][8][4])
{
    const u32 lrow  = (u32)(lid & 15) * 128;
    const u32 lkh   = (u32)((lid >> 4) << 4);
    const u32 brow0 = (u32)kw * 128 + lrow;
#pragma unroll
    for (int ks = 0; ks < 4; ks++) {
        const u32 kb = (u32)(ks * 32) + lkh;
        u32 ah[2][4], al[2][4], bh[4][4];
#pragma unroll
        for (int mt = 0; mt < 2; mt++) {
            u32 off = SWZ((u32)((wm * 32 + mt * 16) * 128) + lrow + kb);
            ldm_x4(ah[mt], sb + offA + off);
            ldm_x4(al[mt], sb + offA + ASZ + off);
        }
#pragma unroll
        for (int bt = 0; bt < 4; bt++) {
            u32 off = SWZ((u32)((wn * 64 + bt * 16) * 128) + brow0 + kb);
            ldm_x4(bh[bt], sb + offB + off);
        }
#pragma unroll
        for (int mt = 0; mt < 2; mt++)
#pragma unroll
            for (int bt = 0; bt < 4; bt++)
#pragma unroll
                for (int j = 0; j < 2; j++) {
                    u32 BH2[2] = { bh[bt][j], bh[bt][j + 2] };
                    float* d = acc[mt][bt * 2 + j];
                    mma16816(d, ah[mt], BH2);
                    mma16816(d, al[mt], BH2);
                }
    }
}

// ---------------- fused branch-PAIR 3x3 conv + BN + relu ----------------
// grid = (H=128, B=8, pair=2); per-warp-pair A pipeline, 1 CTA sync per chunk.
__global__ __launch_bounds__(512, 1)
void k_conv_branch(const float* __restrict__ x,
                   const float* __restrict__ ob0, const float* __restrict__ ob1,
                   const float* __restrict__ ob2, const float* __restrict__ ob3)
{
    extern __shared__ char smem_raw[];
    u32 sb = smem_u32(smem_raw);
    const int h  = blockIdx.x;
    const int b  = blockIdx.y;
    const int bz = blockIdx.z;
    const int tid = threadIdx.x;
    const int wid = tid >> 5, lid = tid & 31;
    const int wm = wid >> 1, wn = wid & 1;
    const size_t HIOFF = 9 * 16384;                  // +1 branch in g_wA
    const __half2* wbase = wn ? g_wAl : g_wAh;

    float acc[2][8][4];
#pragma unroll
    for (int i = 0; i < 2; i++)
#pragma unroll
        for (int j = 0; j < 8; j++)
#pragma unroll
            for (int k = 0; k < 4; k++) acc[i][j][k] = 0.f;

    BReg breg;
    ldg_B(breg, tid, x, CINC, b, 0, h - 1);          // chunk 0: kh=0, c0=0
    {   // step 0 A copy (own plane, own rows)
        size_t t0 = (size_t)(bz * 18) * 16384;
        build_A_warp(sb, OFF_A0, wm, wn, lid, wbase + t0, 128, 0, HIOFF);
        CPA_COMMIT();
    }

    for (int ch = 0; ch < 12; ch++) {
        u32 offB = (ch & 1) ? OFF_B1 : OFF_B0;
        st_B(breg, sb, offB, tid);
        __syncthreads();                             // only CTA-wide sync per chunk
        if (ch + 1 < 12) {
            int kh2 = (ch + 1) >> 2, c02 = ((ch + 1) & 3) * 64;
            ldg_B(breg, tid, x, CINC, b, c02, h + kh2 - 1);    // drains under MMAs
        }
#pragma unroll
        for (int kw = 0; kw < 3; kw++) {
            int step = ch * 3 + kw;
            CPA_WAIT0();                             // own copies of tap `step`
            PAIR_BAR(1 + wm);                        // partner's plane visible; buffer freed
            if (step + 1 < 36) {
                int s2 = step + 1, ch2 = s2 / 3, kw2 = s2 - ch2 * 3;
                int kh2 = ch2 >> 2, c02 = (ch2 & 3) * 64;
                size_t tn = (size_t)(bz * 18 + kh2 * 3 + kw2) * 16384;
                build_A_warp(sb, (s2 & 1) ? OFF_A1 : OFF_A0, wm, wn, lid,
                             wbase + tn, 128, c02 >> 1, HIOFF);
                CPA_COMMIT();
            }
            mma_chunk(sb, (step & 1) ? OFF_A1 : OFF_A0, offB, kw, wm, wn, lid, acc);
        }
    }

    const float* obs[4] = { ob0, ob1, ob2, ob3 };
#pragma unroll
    for (int mt = 0; mt < 2; mt++) {
        int r0 = wm * 32 + mt * 16 + (lid >> 2);     // 0..255
#pragma unroll
        for (int half = 0; half < 2; half++) {
            int co  = r0 + half * 8;
            int brl = co >> 7;
            int cob = co & 127;
            float sh = obs[2 * bz + brl][cob];
            float* row = g_y[2 * bz + brl] + ((size_t)(b * CMID + cob) * HH + h) * WW;
#pragma unroll
            for (int nf = 0; nf < 8; nf++) {
                int px = wn * 64 + nf * 8 + 2 * (lid & 3);
                float2 v;
                v.x = fmaxf(acc[mt][nf][half * 2 + 0] + sh, 0.f);
                v.y = fmaxf(acc[mt][nf][half * 2 + 1] + sh, 0.f);
                *(float2*)(row + px) = v;
            }
        }
    }
}

// ---------------- scans along W (warp-per-row, float4 + shfl scan) ----------------
__global__ void k_scan_w()
{
    int bc   = blockIdx.x;
    int wq   = threadIdx.x >> 5;
    int lane = threadIdx.x & 31;
    const size_t plane = (size_t)bc * HH * WW;
    for (int hr = wq; hr < HH; hr += 16) {
        const float4* yl4 = (const float4*)(g_y[0] + plane + (size_t)hr * WW);
        const float4* yr4 = (const float4*)(g_y[1] + plane + (size_t)hr * WW);
        float4 a = yl4[lane];
        float4 r = yr4[lane];
        float p0 = r.x, p1 = fmaxf(p0, r.y), p2 = fmaxf(p1, r.z), p3 = fmaxf(p2, r.w);
        float m = p3;
#pragma unroll
        for (int o = 1; o < 32; o <<= 1) {
            float v = __shfl_up_sync(0xffffffffu, m, o);
            if (lane >= o) m = fmaxf(m, v);
        }
        float ex = __shfl_up_sync(0xffffffffu, m, 1);
        if (lane == 0) ex = -INFINITY;
        float q3 = a.w, q2 = fmaxf(q3, a.z), q1 = fmaxf(q2, a.y), q0 = fmaxf(q1, a.x);
        float mm = q0;
#pragma unroll
        for (int o = 1; o < 32; o <<= 1) {
            float v = __shfl_down_sync(0xffffffffu, mm, o);
            if (lane + o < 32) mm = fmaxf(mm, v);
        }
        float exr = __shfl_down_sync(0xffffffffu, mm, 1);
        if (lane == 31) exr = -INFINITY;
        float4 o4;
        o4.x = fmaxf(ex, p0) + fmaxf(exr, q0);
        o4.y = fmaxf(ex, p1) + fmaxf(exr, q1);
        o4.z = fmaxf(ex, p2) + fmaxf(exr, q2);
        o4.w = fmaxf(ex, p3) + fmaxf(exr, q3);
        ((float4*)(g_S + plane + (size_t)hr * WW))[lane] = o4;
    }
}

// ---------------- scans along H (coalesced columns) ----------------
__global__ void k_scan_h()
{
    int bc = blockIdx.x;
    int w  = threadIdx.x;
    const float* yt = g_y[2] + (size_t)bc * (HH * WW) + w;
    const float* yv = g_y[3] + (size_t)bc * (HH * WW) + w;
    float* Sp = g_S + (size_t)bc * (HH * WW) + w;
    float m = -INFINITY;
    for (int hq = HH - 1; hq >= 0; --hq) { m = fmaxf(m, yt[hq * WW]); Sp[hq * WW] += m; }
    m = -INFINITY;
    for (int hq = 0; hq < HH; ++hq)      { m = fmaxf(m, yv[hq * WW]); Sp[hq * WW] += m; }
}

// ---------------- conv2 3x3 over S + 1x1 skip over x + relu -> out ----------------
// grid = (H=128, B=8, 1), 512 threads, M=256, per-warp-pair A pipeline
__device__ __forceinline__ void prefetch_A_out_warp(u32 sb, int wm, int wn, int lane, int s)
{
    u32 offA = (s & 1) ? OFF_A1 : OFF_A0;
    if (s < 18) {
        int ch = s / 3, kw = s - ch * 3;
        int kh = ch >> 1, c0 = (ch & 1) * 64;
        size_t tn = (size_t)(kh * 3 + kw) * 256 * 64;
        build_A_warp(sb, offA, wm, wn, lane,
                     (wn ? g_w2l : g_w2h) + tn, 64, c0 >> 1, (size_t)128 * 64);
    } else {
        int c = s - 18;
        build_A_warp(sb, offA, wm, wn, lane,
                     (wn ? g_w1l : g_w1h), 128, c * 32, (size_t)128 * 128);
    }
    CPA_COMMIT();
}

__global__ __launch_bounds__(512, 1)
void k_conv_out(const float* __restrict__ x,
                const float* __restrict__ o2v, const float* __restrict__ o1v,
                float* __restrict__ out)
{
    extern __shared__ char smem_raw[];
    u32 sb = smem_u32(smem_raw);
    const int h  = blockIdx.x;
    const int b  = blockIdx.y;
    const int tid = threadIdx.x;
    const int wid = tid >> 5, lid = tid & 31;
    const int wm = wid >> 1, wn = wid & 1;

    float acc[2][8][4];
#pragma unroll
    for (int i = 0; i < 2; i++)
#pragma unroll
        for (int j = 0; j < 8; j++)
#pragma unroll
            for (int k = 0; k < 4; k++) acc[i][j][k] = 0.f;

    BReg breg;
    ldg_B(breg, tid, g_S, CMID, b, 0, h - 1);        // phase1 chunk 0
    prefetch_A_out_warp(sb, wm, wn, lid, 0);

    // phase 1: 3x3 conv over g_S (6 chunks x 3 kw = 18 steps)
    for (int ch = 0; ch < 6; ch++) {
        u32 offB = (ch & 1) ? OFF_B1 : OFF_B0;
        st_B(breg, sb, offB, tid);
        __syncthreads();
        if (ch + 1 < 6) {
            int kh2 = (ch + 1) >> 1, c02 = ((ch + 1) & 1) * 64;
            ldg_B(breg, tid, g_S, CMID, b, c02, h + kh2 - 1);
        } else {
            ldg_B(breg, tid, x, CINC, b, 0, h);      // bridge to phase 2
        }
#pragma unroll
        for (int kw = 0; kw < 3; kw++) {
            int step = ch * 3 + kw;
            CPA_WAIT0();
            PAIR_BAR(1 + wm);
            if (step + 1 < 22) prefetch_A_out_warp(sb, wm, wn, lid, step + 1);
            mma_chunk(sb, (step & 1) ? OFF_A1 : OFF_A0, offB, kw, wm, wn, lid, acc);
        }
    }
    // phase 2: 1x1 skip over x (4 chunks, 1 step each; brow offset 1 = unshifted)
    for (int c = 0; c < 4; c++) {
        int ch = 6 + c;
        u32 offB = (ch & 1) ? OFF_B1 : OFF_B0;
        st_B(breg, sb, offB, tid);
        __syncthreads();
        if (c + 1 < 4) ldg_B(breg, tid, x, CINC, b, (c + 1) * 64, h);
        int step = 18 + c;
        CPA_WAIT0();
        PAIR_BAR(1 + wm);
        if (step + 1 < 22) prefetch_A_out_warp(sb, wm, wn, lid, step + 1);
        mma_chunk(sb, (step & 1) ? OFF_A1 : OFF_A0, offB, 1, wm, wn, lid, acc);
    }

#pragma unroll
    for (int mt = 0; mt < 2; mt++) {
        int r0 = wm * 32 + mt * 16 + (lid >> 2);
#pragma unroll
        for (int half = 0; half < 2; half++) {
            int co = r0 + half * 8;                  // 0..255
            float sh = o2v[co] + o1v[co];
            float* row = out + ((size_t)(b * COUTC + co) * HH + h) * WW;
#pragma unroll
            for (int nf = 0; nf < 8; nf++) {
                int px = wn * 64 + nf * 8 + 2 * (lid & 3);
                float2 v;
                v.x = fmaxf(acc[mt][nf][half * 2 + 0] + sh, 0.f);
                v.y = fmaxf(acc[mt][nf][half * 2 + 1] + sh, 0.f);
                *(float2*)(row + px) = v;
            }
        }
    }
}

// ---------------- launch ----------------
// NOTE: launch order puts k_conv_branch at index 5 so ncu (-s 5 -c 1) captures it.
extern "C" void kernel_launch(void* const* d_in, const int* in_sizes, int n_in,
                              void* d_out, int out_size)
{
    const float* x   = (const float*)d_in[0];
    const float* w_l = (const float*)d_in[1];
    const float* s_l = (const float*)d_in[2];
    const float* o_l = (const float*)d_in[3];
    const float* w_r = (const float*)d_in[4];
    const float* s_r = (const float*)d_in[5];
    const float* o_r = (const float*)d_in[6];
    const float* w_t = (const float*)d_in[7];
    const float* s_t = (const float*)d_in[8];
    const float* o_t = (const float*)d_in[9];
    const float* w_b = (const float*)d_in[10];
    const float* s_b = (const float*)d_in[11];
    const float* o_b = (const float*)d_in[12];
    const float* w2  = (const float*)d_in[13];
    const float* s2  = (const float*)d_in[14];
    const float* o2  = (const float*)d_in[15];
    const float* w1  = (const float*)d_in[16];
    const float* s1  = (const float*)d_in[17];
    const float* o1  = (const float*)d_in[18];
    float* out = (float*)d_out;

    cudaFuncSetAttribute(k_conv_branch, cudaFuncAttributeMaxDynamicSharedMemorySize, SMEM_BYTES);
    cudaFuncSetAttribute(k_conv_out,    cudaFuncAttributeMaxDynamicSharedMemorySize, SMEM_BYTES);

    k_repack_br<<<576, 256>>>(w_l, s_l, 0);          // 0
    k_repack_br<<<576, 256>>>(w_r, s_r, 1);          // 1
    k_repack_br<<<576, 256>>>(w_t, s_t, 2);          // 2
    k_repack_br<<<576, 256>>>(w_b, s_b, 3);          // 3
    k_repack_w2<<<576, 256>>>(w2, s2);               // 4
    dim3 g1(HH, BN, 2);
    k_conv_branch<<<g1, 512, SMEM_BYTES>>>(x, o_l, o_r, o_t, o_b);   // 5 <- ncu target
    k_repack_w1<<<128, 256>>>(w1, s1);               // 6 (needed only by conv_out)
    k_scan_w<<<BN * CMID, 512>>>();
    k_scan_h<<<BN * CMID, 128>>>();
    dim3 g3(HH, BN, 1);
    k_conv_out<<<g3, 512, SMEM_BYTES>>>(x, o2, o1, out);
}

// round 14
// speedup vs baseline: 2.4347x; 1.7749x over previous
#include <cuda_runtime.h>
#include <cuda_fp16.h>
#include <cstdint>
#include <math.h>

#define BN    8
#define CINC  256
#define CMID  128
#define COUTC 256
#define HH    128
#define WW    128
#define HWSZ  16384

typedef uint32_t u32;

// ---------------- scratch (static __device__ — allocation-free) ----------------
__device__ float g_y[4][BN * CMID * HH * WW];  // branch conv outputs (post-relu)
__device__ float g_S[BN * CMID * HH * WW];     // sum of 4 scanned branches
// fp16 weights (single plane): branch [tap=br*9+kh*3+kw][co=128][cipair=128]
__device__ __align__(16) __half2 g_wA[36 * 128 * 128];
__device__ __align__(16) __half2 g_w2[9 * 256 * 64];   // [t][co=256][cipair=64]
__device__ __align__(16) __half2 g_w1[256 * 128];      // [co=256][cipair=128]

// ---------------- helpers ----------------
__device__ __forceinline__ u32 smem_u32(const void* p) {
    u32 a;
    asm("{ .reg .u64 t; cvta.to.shared.u64 t, %1; cvt.u32.u64 %0, t; }" : "=r"(a) : "l"(p));
    return a;
}

// XOR swizzle: byte bits [6:4] ^= bits [9:7]  (rows are 128B)
#define SWZ(off) ((off) ^ (((off) >> 3) & 0x70))

__device__ __forceinline__ void ldm_x4(u32* r, u32 addr) {
    asm volatile("ldmatrix.sync.aligned.m8n8.x4.shared.b16 {%0,%1,%2,%3}, [%4];"
                 : "=r"(r[0]), "=r"(r[1]), "=r"(r[2]), "=r"(r[3]) : "r"(addr));
}
__device__ __forceinline__ void mma16816(float* d, const u32* a, const u32* b) {
    asm volatile("mma.sync.aligned.m16n8k16.row.col.f32.f16.f16.f32 "
                 "{%0,%1,%2,%3}, {%4,%5,%6,%7}, {%8,%9}, {%0,%1,%2,%3};"
                 : "+f"(d[0]), "+f"(d[1]), "+f"(d[2]), "+f"(d[3])
                 : "r"(a[0]), "r"(a[1]), "r"(a[2]), "r"(a[3]), "r"(b[0]), "r"(b[1]));
}
__device__ __forceinline__ void cpa16(u32 d, const void* s) {
    asm volatile("cp.async.cg.shared.global [%0], [%1], 16;" :: "r"(d), "l"(s));
}
#define CPA_COMMIT() asm volatile("cp.async.commit_group;" ::: "memory")
#define CPA_WAIT0()  asm volatile("cp.async.wait_group 0;" ::: "memory")
#define PAIR_BAR(id) asm volatile("bar.sync %0, 64;" :: "r"(id) : "memory")

// smem: two single-plane A buffers (256 rows x 128B) + two single-plane B buffers
#define BSZ    16896                    // 132 * 128 bytes
#define ASZ    32768                    // 256 * 128 bytes
#define OFF_A0 0
#define OFF_A1 32768
#define OFF_B0 65536
#define OFF_B1 (65536 + BSZ)            // 82432
#define SMEM_BYTES (OFF_B1 + BSZ)       // 99328

// pack two fp32 -> fp16x2 word and store to smem
__device__ __forceinline__ void stpack(float v0, float v1, u32 addr) {
    __half h0 = __float2half(v0), h1 = __float2half(v1);
    u32 hv;
    asm("mov.b32 %0, {%1, %2};" : "=r"(hv) : "h"(*(unsigned short*)&h0), "h"(*(unsigned short*)&h1));
    asm volatile("st.shared.b32 [%0], %1;" :: "r"(addr), "r"(hv) : "memory");
}

// ---------------- weight repack (+BN scale fold, fp16) ----------------
__global__ void k_repack_br(const float* __restrict__ w, const float* __restrict__ s, int br)
{
    int slot = blockIdx.x * 256 + threadIdx.x;       // 9*128*128
    if (slot >= 147456) return;
    int pair = slot & 127;
    int co   = (slot >> 7) & 127;
    int t    = slot >> 14;
    int kh = t / 3, kw = t % 3;
    int ci = pair * 2;
    float sc = s[co];
    float v0 = w[((co * CINC + ci)     * 3 + kh) * 3 + kw] * sc;
    float v1 = w[((co * CINC + ci + 1) * 3 + kh) * 3 + kw] * sc;
    g_wA[((br * 9 + t) * 128 + co) * 128 + pair] =
        __halves2half2(__float2half(v0), __float2half(v1));
}

__global__ void k_repack_w2(const float* __restrict__ w, const float* __restrict__ s)
{
    int slot = blockIdx.x * 256 + threadIdx.x;       // 9*256*64
    if (slot >= 147456) return;
    int pair = slot & 63;
    int co   = (slot >> 6) & 255;
    int t    = slot >> 14;
    int kh = t / 3, kw = t % 3;
    int ci = pair * 2;
    float sc = s[co];
    float v0 = w[((co * CMID + ci)     * 3 + kh) * 3 + kw] * sc;
    float v1 = w[((co * CMID + ci + 1) * 3 + kh) * 3 + kw] * sc;
    g_w2[(t * 256 + co) * 64 + pair] =
        __halves2half2(__float2half(v0), __float2half(v1));
}

__global__ void k_repack_w1(const float* __restrict__ w, const float* __restrict__ s)
{
    int slot = blockIdx.x * 256 + threadIdx.x;       // 256*128
    if (slot >= 32768) return;
    int pair = slot & 127;
    int co   = slot >> 7;
    int ci = pair * 2;
    float sc = s[co];
    float v0 = w[co * CINC + ci]     * sc;
    float v1 = w[co * CINC + ci + 1] * sc;
    g_w1[co * 128 + pair] =
        __halves2half2(__float2half(v0), __float2half(v1));
}

// ---------------- per-warp A copy: 16 rows x 128B (pair covers 32 rows) ----------------
__device__ __forceinline__ void build_A_warp(u32 sb, u32 offA, int wm, int wn, int lane,
                                             const __half2* __restrict__ wsrc,
                                             int rsp, int pair0, size_t hi_off)
{
#pragma unroll
    for (int q = 0; q < 4; q++) {
        int slot = lane + 32 * q;            // 0..127
        int co = wm * 32 + wn * 16 + (slot >> 3);
        int c  = slot & 7;
        u32 d = SWZ((u32)(co * 128 + c * 16));
        size_t idx = (co < 128 ? (size_t)co * rsp : hi_off + (size_t)(co - 128) * rsp) + pair0;
        cpa16(sb + offA + d, (const char*)(wsrc + idx) + c * 16);
    }
}

// ---------------- B staged through registers ----------------
struct BReg { float m[16]; float t0, t1; };

__device__ __forceinline__ void ldg_B(BReg& r, int tid, const float* __restrict__ src,
                                      int nchan, int b, int c0, int srow)
{
    const size_t HW = (size_t)HWSZ;
    bool rowok = (srow >= 0) && (srow < HH);
    const float* base = src + ((size_t)(b * nchan + c0) * HH + (rowok ? srow : 0)) * WW;
    int p  = tid & 127;
    int gp = tid >> 7;
    int spx = p - 1;
    bool okm = rowok && (spx >= 0);
    const float* bp = base + spx;
#pragma unroll
    for (int q = 0; q < 8; q++) {
        int cil = gp * 16 + 2 * q;
        r.m[2 * q]     = okm ? bp[(size_t)cil * HW] : 0.f;
        r.m[2 * q + 1] = okm ? bp[(size_t)(cil + 1) * HW] : 0.f;
    }
    if (tid < 128) {
        int rr = 128 + (tid >> 5);
        int pc = tid & 31;
        int cil = 2 * pc;
        int sp2 = rr - 1;
        bool ok = rowok && (sp2 < WW);
        r.t0 = ok ? base[(size_t)cil * HW + sp2] : 0.f;
        r.t1 = ok ? base[(size_t)(cil + 1) * HW + sp2] : 0.f;
    }
}

__device__ __forceinline__ void st_B(const BReg& r, u32 sb, u32 offB, int tid)
{
    int p  = tid & 127;
    int gp = tid >> 7;
#pragma unroll
    for (int q = 0; q < 8; q++) {
        int cil = gp * 16 + 2 * q;
        stpack(r.m[2 * q], r.m[2 * q + 1], sb + offB + SWZ((u32)(p * 128 + 2 * cil)));
    }
    if (tid < 128) {
        int rr = 128 + (tid >> 5);
        int pc = tid & 31;
        stpack(r.t0, r.t1, sb + offB + SWZ((u32)(rr * 128 + 4 * pc)));
    }
}

// ---------------- mma over one 64-k chunk; M=256, warp = 32co x 64px, 1 product ----------------
// 16 warps: wm = wid>>1 (0..7), wn = wid&1 (0..1)
__device__ __forceinline__ void mma_chunk(u32 sb, u32 offA, u32 offB, int kw,
                                          int wm, int wn, int lid, float acc[2][8][4])
{
    const u32 lrow  = (u32)(lid & 15) * 128;
    const u32 lkh   = (u32)((lid >> 4) << 4);
    const u32 brow0 = (u32)kw * 128 + lrow;
#pragma unroll
    for (int ks = 0; ks < 4; ks++) {
        const u32 kb = (u32)(ks * 32) + lkh;
        u32 ah[2][4], bh[4][4];
#pragma unroll
        for (int mt = 0; mt < 2; mt++) {
            u32 off = SWZ((u32)((wm * 32 + mt * 16) * 128) + lrow + kb);
            ldm_x4(ah[mt], sb + offA + off);
        }
#pragma unroll
        for (int bt = 0; bt < 4; bt++) {
            u32 off = SWZ((u32)((wn * 64 + bt * 16) * 128) + brow0 + kb);
            ldm_x4(bh[bt], sb + offB + off);
        }
#pragma unroll
        for (int mt = 0; mt < 2; mt++)
#pragma unroll
            for (int bt = 0; bt < 4; bt++)
#pragma unroll
                for (int j = 0; j < 2; j++) {
                    u32 BH2[2] = { bh[bt][j], bh[bt][j + 2] };
                    mma16816(acc[mt][bt * 2 + j], ah[mt], BH2);
                }
    }
}

// ---------------- fused branch-PAIR 3x3 conv + BN + relu ----------------
// grid = (H=128, B=8, pair=2); per-warp-pair A pipeline, 1 CTA sync per chunk.
__global__ __launch_bounds__(512, 1)
void k_conv_branch(const float* __restrict__ x,
                   const float* __restrict__ ob0, const float* __restrict__ ob1,
                   const float* __restrict__ ob2, const float* __restrict__ ob3)
{
    extern __shared__ char smem_raw[];
    u32 sb = smem_u32(smem_raw);
    const int h  = blockIdx.x;
    const int b  = blockIdx.y;
    const int bz = blockIdx.z;
    const int tid = threadIdx.x;
    const int wid = tid >> 5, lid = tid & 31;
    const int wm = wid >> 1, wn = wid & 1;
    const size_t HIOFF = 9 * 16384;                  // +1 branch in g_wA

    float acc[2][8][4];
#pragma unroll
    for (int i = 0; i < 2; i++)
#pragma unroll
        for (int j = 0; j < 8; j++)
#pragma unroll
            for (int k = 0; k < 4; k++) acc[i][j][k] = 0.f;

    BReg breg;
    ldg_B(breg, tid, x, CINC, b, 0, h - 1);          // chunk 0: kh=0, c0=0
    {   // step 0 A copy (own rows)
        size_t t0 = (size_t)(bz * 18) * 16384;
        build_A_warp(sb, OFF_A0, wm, wn, lid, g_wA + t0, 128, 0, HIOFF);
        CPA_COMMIT();
    }

    for (int ch = 0; ch < 12; ch++) {
        u32 offB = (ch & 1) ? OFF_B1 : OFF_B0;
        st_B(breg, sb, offB, tid);
        __syncthreads();                             // only CTA-wide sync per chunk
        if (ch + 1 < 12) {
            int kh2 = (ch + 1) >> 2, c02 = ((ch + 1) & 3) * 64;
            ldg_B(breg, tid, x, CINC, b, c02, h + kh2 - 1);    // drains under MMAs
        }
#pragma unroll
        for (int kw = 0; kw < 3; kw++) {
            int step = ch * 3 + kw;
            CPA_WAIT0();                             // own copies of tap `step`
            PAIR_BAR(1 + wm);                        // partner rows visible; buffer freed
            if (step + 1 < 36) {
                int s2 = step + 1, ch2 = s2 / 3, kw2 = s2 - ch2 * 3;
                int kh2 = ch2 >> 2, c02 = (ch2 & 3) * 64;
                size_t tn = (size_t)(bz * 18 + kh2 * 3 + kw2) * 16384;
                build_A_warp(sb, (s2 & 1) ? OFF_A1 : OFF_A0, wm, wn, lid,
                             g_wA + tn, 128, c02 >> 1, HIOFF);
                CPA_COMMIT();
            }
            mma_chunk(sb, (step & 1) ? OFF_A1 : OFF_A0, offB, kw, wm, wn, lid, acc);
        }
    }

    const float* obs[4] = { ob0, ob1, ob2, ob3 };
#pragma unroll
    for (int mt = 0; mt < 2; mt++) {
        int r0 = wm * 32 + mt * 16 + (lid >> 2);     // 0..255
#pragma unroll
        for (int half = 0; half < 2; half++) {
            int co  = r0 + half * 8;
            int brl = co >> 7;
            int cob = co & 127;
            float sh = obs[2 * bz + brl][cob];
            float* row = g_y[2 * bz + brl] + ((size_t)(b * CMID + cob) * HH + h) * WW;
#pragma unroll
            for (int nf = 0; nf < 8; nf++) {
                int px = wn * 64 + nf * 8 + 2 * (lid & 3);
                float2 v;
                v.x = fmaxf(acc[mt][nf][half * 2 + 0] + sh, 0.f);
                v.y = fmaxf(acc[mt][nf][half * 2 + 1] + sh, 0.f);
                *(float2*)(row + px) = v;
            }
        }
    }
}

// ---------------- scans along W (warp-per-row, float4 + shfl scan) ----------------
__global__ void k_scan_w()
{
    int bc   = blockIdx.x;
    int wq   = threadIdx.x >> 5;
    int lane = threadIdx.x & 31;
    const size_t plane = (size_t)bc * HH * WW;
    for (int hr = wq; hr < HH; hr += 16) {
        const float4* yl4 = (const float4*)(g_y[0] + plane + (size_t)hr * WW);
        const float4* yr4 = (const float4*)(g_y[1] + plane + (size_t)hr * WW);
        float4 a = yl4[lane];
        float4 r = yr4[lane];
        float p0 = r.x, p1 = fmaxf(p0, r.y), p2 = fmaxf(p1, r.z), p3 = fmaxf(p2, r.w);
        float m = p3;
#pragma unroll
        for (int o = 1; o < 32; o <<= 1) {
            float v = __shfl_up_sync(0xffffffffu, m, o);
            if (lane >= o) m = fmaxf(m, v);
        }
        float ex = __shfl_up_sync(0xffffffffu, m, 1);
        if (lane == 0) ex = -INFINITY;
        float q3 = a.w, q2 = fmaxf(q3, a.z), q1 = fmaxf(q2, a.y), q0 = fmaxf(q1, a.x);
        float mm = q0;
#pragma unroll
        for (int o = 1; o < 32; o <<= 1) {
            float v = __shfl_down_sync(0xffffffffu, mm, o);
            if (lane + o < 32) mm = fmaxf(mm, v);
        }
        float exr = __shfl_down_sync(0xffffffffu, mm, 1);
        if (lane == 31) exr = -INFINITY;
        float4 o4;
        o4.x = fmaxf(ex, p0) + fmaxf(exr, q0);
        o4.y = fmaxf(ex, p1) + fmaxf(exr, q1);
        o4.z = fmaxf(ex, p2) + fmaxf(exr, q2);
        o4.w = fmaxf(ex, p3) + fmaxf(exr, q3);
        ((float4*)(g_S + plane + (size_t)hr * WW))[lane] = o4;
    }
}

// ---------------- scans along H (coalesced columns) ----------------
__global__ void k_scan_h()
{
    int bc = blockIdx.x;
    int w  = threadIdx.x;
    const float* yt = g_y[2] + (size_t)bc * (HH * WW) + w;
    const float* yv = g_y[3] + (size_t)bc * (HH * WW) + w;
    float* Sp = g_S + (size_t)bc * (HH * WW) + w;
    float m = -INFINITY;
    for (int hq = HH - 1; hq >= 0; --hq) { m = fmaxf(m, yt[hq * WW]); Sp[hq * WW] += m; }
    m = -INFINITY;
    for (int hq = 0; hq < HH; ++hq)      { m = fmaxf(m, yv[hq * WW]); Sp[hq * WW] += m; }
}

// ---------------- conv2 3x3 over S + 1x1 skip over x + relu -> out ----------------
// grid = (H=128, B=8, 1), 512 threads, M=256, per-warp-pair A pipeline
__device__ __forceinline__ void prefetch_A_out_warp(u32 sb, int wm, int wn, int lane, int s)
{
    u32 offA = (s & 1) ? OFF_A1 : OFF_A0;
    if (s < 18) {
        int ch = s / 3, kw = s - ch * 3;
        int kh = ch >> 1, c0 = (ch & 1) * 64;
        size_t tn = (size_t)(kh * 3 + kw) * 256 * 64;
        build_A_warp(sb, offA, wm, wn, lane, g_w2 + tn, 64, c0 >> 1, (size_t)128 * 64);
    } else {
        int c = s - 18;
        build_A_warp(sb, offA, wm, wn, lane, g_w1, 128, c * 32, (size_t)128 * 128);
    }
    CPA_COMMIT();
}

__global__ __launch_bounds__(512, 1)
void k_conv_out(const float* __restrict__ x,
                const float* __restrict__ o2v, const float* __restrict__ o1v,
                float* __restrict__ out)
{
    extern __shared__ char smem_raw[];
    u32 sb = smem_u32(smem_raw);
    const int h  = blockIdx.x;
    const int b  = blockIdx.y;
    const int tid = threadIdx.x;
    const int wid = tid >> 5, lid = tid & 31;
    const int wm = wid >> 1, wn = wid & 1;

    float acc[2][8][4];
#pragma unroll
    for (int i = 0; i < 2; i++)
#pragma unroll
        for (int j = 0; j < 8; j++)
#pragma unroll
            for (int k = 0; k < 4; k++) acc[i][j][k] = 0.f;

    BReg breg;
    ldg_B(breg, tid, g_S, CMID, b, 0, h - 1);        // phase1 chunk 0
    prefetch_A_out_warp(sb, wm, wn, lid, 0);

    // phase 1: 3x3 conv over g_S (6 chunks x 3 kw = 18 steps)
    for (int ch = 0; ch < 6; ch++) {
        u32 offB = (ch & 1) ? OFF_B1 : OFF_B0;
        st_B(breg, sb, offB, tid);
        __syncthreads();
        if (ch + 1 < 6) {
            int kh2 = (ch + 1) >> 1, c02 = ((ch + 1) & 1) * 64;
            ldg_B(breg, tid, g_S, CMID, b, c02, h + kh2 - 1);
        } else {
            ldg_B(breg, tid, x, CINC, b, 0, h);      // bridge to phase 2
        }
#pragma unroll
        for (int kw = 0; kw < 3; kw++) {
            int step = ch * 3 + kw;
            CPA_WAIT0();
            PAIR_BAR(1 + wm);
            if (step + 1 < 22) prefetch_A_out_warp(sb, wm, wn, lid, step + 1);
            mma_chunk(sb, (step & 1) ? OFF_A1 : OFF_A0, offB, kw, wm, wn, lid, acc);
        }
    }
    // phase 2: 1x1 skip over x (4 chunks, 1 step each; brow offset 1 = unshifted)
    for (int c = 0; c < 4; c++) {
        int ch = 6 + c;
        u32 offB = (ch & 1) ? OFF_B1 : OFF_B0;
        st_B(breg, sb, offB, tid);
        __syncthreads();
        if (c + 1 < 4) ldg_B(breg, tid, x, CINC, b, (c + 1) * 64, h);
        int step = 18 + c;
        CPA_WAIT0();
        PAIR_BAR(1 + wm);
        if (step + 1 < 22) prefetch_A_out_warp(sb, wm, wn, lid, step + 1);
        mma_chunk(sb, (step & 1) ? OFF_A1 : OFF_A0, offB, 1, wm, wn, lid, acc);
    }

#pragma unroll
    for (int mt = 0; mt < 2; mt++) {
        int r0 = wm * 32 + mt * 16 + (lid >> 2);
#pragma unroll
        for (int half = 0; half < 2; half++) {
            int co = r0 + half * 8;                  // 0..255
            float sh = o2v[co] + o1v[co];
            float* row = out + ((size_t)(b * COUTC + co) * HH + h) * WW;
#pragma unroll
            for (int nf = 0; nf < 8; nf++) {
                int px = wn * 64 + nf * 8 + 2 * (lid & 3);
                float2 v;
                v.x = fmaxf(acc[mt][nf][half * 2 + 0] + sh, 0.f);
                v.y = fmaxf(acc[mt][nf][half * 2 + 1] + sh, 0.f);
                *(float2*)(row + px) = v;
            }
        }
    }
}

// ---------------- launch ----------------
// NOTE: launch order puts k_conv_branch at index 5 so ncu (-s 5 -c 1) captures it.
extern "C" void kernel_launch(void* const* d_in, const int* in_sizes, int n_in,
                              void* d_out, int out_size)
{
    const float* x   = (const float*)d_in[0];
    const float* w_l = (const float*)d_in[1];
    const float* s_l = (const float*)d_in[2];
    const float* o_l = (const float*)d_in[3];
    const float* w_r = (const float*)d_in[4];
    const float* s_r = (const float*)d_in[5];
    const float* o_r = (const float*)d_in[6];
    const float* w_t = (const float*)d_in[7];
    const float* s_t = (const float*)d_in[8];
    const float* o_t = (const float*)d_in[9];
    const float* w_b = (const float*)d_in[10];
    const float* s_b = (const float*)d_in[11];
    const float* o_b = (const float*)d_in[12];
    const float* w2  = (const float*)d_in[13];
    const float* s2  = (const float*)d_in[14];
    const float* o2  = (const float*)d_in[15];
    const float* w1  = (const float*)d_in[16];
    const float* s1  = (const float*)d_in[17];
    const float* o1  = (const float*)d_in[18];
    float* out = (float*)d_out;

    cudaFuncSetAttribute(k_conv_branch, cudaFuncAttributeMaxDynamicSharedMemorySize, SMEM_BYTES);
    cudaFuncSetAttribute(k_conv_out,    cudaFuncAttributeMaxDynamicSharedMemorySize, SMEM_BYTES);

    k_repack_br<<<576, 256>>>(w_l, s_l, 0);          // 0
    k_repack_br<<<576, 256>>>(w_r, s_r, 1);          // 1
    k_repack_br<<<576, 256>>>(w_t, s_t, 2);          // 2
    k_repack_br<<<576, 256>>>(w_b, s_b, 3);          // 3
    k_repack_w2<<<576, 256>>>(w2, s2);               // 4
    dim3 g1(HH, BN, 2);
    k_conv_branch<<<g1, 512, SMEM_BYTES>>>(x, o_l, o_r, o_t, o_b);   // 5 <- ncu target
    k_repack_w1<<<128, 256>>>(w1, s1);               // 6 (needed only by conv_out)
    k_scan_w<<<BN * CMID, 512>>>();
    k_scan_h<<<BN * CMID, 128>>>();
    dim3 g3(HH, BN, 1);
    k_conv_out<<<g3, 512, SMEM_BYTES>>>(x, o2, o1, out);
}

// round 15
// speedup vs baseline: 2.4826x; 1.0197x over previous
#include <cuda_runtime.h>
#include <cuda_fp16.h>
#include <cstdint>
#include <math.h>

#define BN    8
#define CINC  256
#define CMID  128
#define COUTC 256
#define HH    128
#define WW    128
#define HWSZ  16384

typedef uint32_t u32;

// ---------------- scratch (static __device__ — allocation-free) ----------------
__device__ float g_y[2][BN * CMID * HH * WW];  // T/B branch conv outputs (post-relu)
__device__ float g_S[BN * CMID * HH * WW];     // sum of scanned branches
// fp16 weights (single plane): branch [tap=br*9+kh*3+kw][co=128][cipair=128]
__device__ __align__(16) __half2 g_wA[36 * 128 * 128];
__device__ __align__(16) __half2 g_w2[9 * 256 * 64];   // [t][co=256][cipair=64]
__device__ __align__(16) __half2 g_w1[256 * 128];      // [co=256][cipair=128]

// ---------------- helpers ----------------
__device__ __forceinline__ u32 smem_u32(const void* p) {
    u32 a;
    asm("{ .reg .u64 t; cvta.to.shared.u64 t, %1; cvt.u32.u64 %0, t; }" : "=r"(a) : "l"(p));
    return a;
}

// XOR swizzle: byte bits [6:4] ^= bits [9:7]  (rows are 128B)
#define SWZ(off) ((off) ^ (((off) >> 3) & 0x70))

__device__ __forceinline__ void ldm_x4(u32* r, u32 addr) {
    asm volatile("ldmatrix.sync.aligned.m8n8.x4.shared.b16 {%0,%1,%2,%3}, [%4];"
                 : "=r"(r[0]), "=r"(r[1]), "=r"(r[2]), "=r"(r[3]) : "r"(addr));
}
__device__ __forceinline__ void mma16816(float* d, const u32* a, const u32* b) {
    asm volatile("mma.sync.aligned.m16n8k16.row.col.f32.f16.f16.f32 "
                 "{%0,%1,%2,%3}, {%4,%5,%6,%7}, {%8,%9}, {%0,%1,%2,%3};"
                 : "+f"(d[0]), "+f"(d[1]), "+f"(d[2]), "+f"(d[3])
                 : "r"(a[0]), "r"(a[1]), "r"(a[2]), "r"(a[3]), "r"(b[0]), "r"(b[1]));
}
__device__ __forceinline__ void cpa16(u32 d, const void* s) {
    asm volatile("cp.async.cg.shared.global [%0], [%1], 16;" :: "r"(d), "l"(s));
}
#define CPA_COMMIT() asm volatile("cp.async.commit_group;" ::: "memory")
#define CPA_WAIT0()  asm volatile("cp.async.wait_group 0;" ::: "memory")
#define PAIR_BAR(id) asm volatile("bar.sync %0, 64;" :: "r"(id) : "memory")

// smem: two single-plane A buffers (256 rows x 128B) + two single-plane B buffers
#define BSZ    16896                    // 132 * 128 bytes
#define ASZ    32768                    // 256 * 128 bytes
#define OFF_A0 0
#define OFF_A1 32768
#define OFF_B0 65536
#define OFF_B1 (65536 + BSZ)            // 82432
#define SMEM_BYTES (OFF_B1 + BSZ)       // 99328  (>= 128*132*4 = 67584 for scan pass)

// pack two fp32 -> fp16x2 word and store to smem
__device__ __forceinline__ void stpack(float v0, float v1, u32 addr) {
    __half h0 = __float2half(v0), h1 = __float2half(v1);
    u32 hv;
    asm("mov.b32 %0, {%1, %2};" : "=r"(hv) : "h"(*(unsigned short*)&h0), "h"(*(unsigned short*)&h1));
    asm volatile("st.shared.b32 [%0], %1;" :: "r"(addr), "r"(hv) : "memory");
}

// ---------------- weight repack (+BN scale fold, fp16) ----------------
__global__ void k_repack_br(const float* __restrict__ w, const float* __restrict__ s, int br)
{
    int slot = blockIdx.x * 256 + threadIdx.x;       // 9*128*128
    if (slot >= 147456) return;
    int pair = slot & 127;
    int co   = (slot >> 7) & 127;
    int t    = slot >> 14;
    int kh = t / 3, kw = t % 3;
    int ci = pair * 2;
    float sc = s[co];
    float v0 = w[((co * CINC + ci)     * 3 + kh) * 3 + kw] * sc;
    float v1 = w[((co * CINC + ci + 1) * 3 + kh) * 3 + kw] * sc;
    g_wA[((br * 9 + t) * 128 + co) * 128 + pair] =
        __halves2half2(__float2half(v0), __float2half(v1));
}

__global__ void k_repack_w2(const float* __restrict__ w, const float* __restrict__ s)
{
    int slot = blockIdx.x * 256 + threadIdx.x;       // 9*256*64
    if (slot >= 147456) return;
    int pair = slot & 63;
    int co   = (slot >> 6) & 255;
    int t    = slot >> 14;
    int kh = t / 3, kw = t % 3;
    int ci = pair * 2;
    float sc = s[co];
    float v0 = w[((co * CMID + ci)     * 3 + kh) * 3 + kw] * sc;
    float v1 = w[((co * CMID + ci + 1) * 3 + kh) * 3 + kw] * sc;
    g_w2[(t * 256 + co) * 64 + pair] =
        __halves2half2(__float2half(v0), __float2half(v1));
}

__global__ void k_repack_w1(const float* __restrict__ w, const float* __restrict__ s)
{
    int slot = blockIdx.x * 256 + threadIdx.x;       // 256*128
    if (slot >= 32768) return;
    int pair = slot & 127;
    int co   = slot >> 7;
    int ci = pair * 2;
    float sc = s[co];
    float v0 = w[co * CINC + ci]     * sc;
    float v1 = w[co * CINC + ci + 1] * sc;
    g_w1[co * 128 + pair] =
        __halves2half2(__float2half(v0), __float2half(v1));
}

// ---------------- per-warp A copy: 16 rows x 128B (pair covers 32 rows) ----------------
__device__ __forceinline__ void build_A_warp(u32 sb, u32 offA, int wm, int wn, int lane,
                                             const __half2* __restrict__ wsrc,
                                             int rsp, int pair0, size_t hi_off)
{
#pragma unroll
    for (int q = 0; q < 4; q++) {
        int slot = lane + 32 * q;            // 0..127
        int co = wm * 32 + wn * 16 + (slot >> 3);
        int c  = slot & 7;
        u32 d = SWZ((u32)(co * 128 + c * 16));
        size_t idx = (co < 128 ? (size_t)co * rsp : hi_off + (size_t)(co - 128) * rsp) + pair0;
        cpa16(sb + offA + d, (const char*)(wsrc + idx) + c * 16);
    }
}

// ---------------- B staged through registers ----------------
struct BReg { float m[16]; float t0, t1; };

__device__ __forceinline__ void ldg_B(BReg& r, int tid, const float* __restrict__ src,
                                      int nchan, int b, int c0, int srow)
{
    const size_t HW = (size_t)HWSZ;
    bool rowok = (srow >= 0) && (srow < HH);
    const float* base = src + ((size_t)(b * nchan + c0) * HH + (rowok ? srow : 0)) * WW;
    int p  = tid & 127;
    int gp = tid >> 7;
    int spx = p - 1;
    bool okm = rowok && (spx >= 0);
    const float* bp = base + spx;
#pragma unroll
    for (int q = 0; q < 8; q++) {
        int cil = gp * 16 + 2 * q;
        r.m[2 * q]     = okm ? bp[(size_t)cil * HW] : 0.f;
        r.m[2 * q + 1] = okm ? bp[(size_t)(cil + 1) * HW] : 0.f;
    }
    if (tid < 128) {
        int rr = 128 + (tid >> 5);
        int pc = tid & 31;
        int cil = 2 * pc;
        int sp2 = rr - 1;
        bool ok = rowok && (sp2 < WW);
        r.t0 = ok ? base[(size_t)cil * HW + sp2] : 0.f;
        r.t1 = ok ? base[(size_t)(cil + 1) * HW + sp2] : 0.f;
    }
}

__device__ __forceinline__ void st_B(const BReg& r, u32 sb, u32 offB, int tid)
{
    int p  = tid & 127;
    int gp = tid >> 7;
#pragma unroll
    for (int q = 0; q < 8; q++) {
        int cil = gp * 16 + 2 * q;
        stpack(r.m[2 * q], r.m[2 * q + 1], sb + offB + SWZ((u32)(p * 128 + 2 * cil)));
    }
    if (tid < 128) {
        int rr = 128 + (tid >> 5);
        int pc = tid & 31;
        stpack(r.t0, r.t1, sb + offB + SWZ((u32)(rr * 128 + 4 * pc)));
    }
}

// ---------------- mma over one 64-k chunk; M=256, warp = 32co x 64px, 1 product ----------------
// 16 warps: wm = wid>>1 (0..7), wn = wid&1 (0..1)
__device__ __forceinline__ void mma_chunk(u32 sb, u32 offA, u32 offB, int kw,
                                          int wm, int wn, int lid, float acc[2][8][4])
{
    const u32 lrow  = (u32)(lid & 15) * 128;
    const u32 lkh   = (u32)((lid >> 4) << 4);
    const u32 brow0 = (u32)kw * 128 + lrow;
#pragma unroll
    for (int ks = 0; ks < 4; ks++) {
        const u32 kb = (u32)(ks * 32) + lkh;
        u32 ah[2][4], bh[4][4];
#pragma unroll
        for (int mt = 0; mt < 2; mt++) {
            u32 off = SWZ((u32)((wm * 32 + mt * 16) * 128) + lrow + kb);
            ldm_x4(ah[mt], sb + offA + off);
        }
#pragma unroll
        for (int bt = 0; bt < 4; bt++) {
            u32 off = SWZ((u32)((wn * 64 + bt * 16) * 128) + brow0 + kb);
            ldm_x4(bh[bt], sb + offB + off);
        }
#pragma unroll
        for (int mt = 0; mt < 2; mt++)
#pragma unroll
            for (int bt = 0; bt < 4; bt++)
#pragma unroll
                for (int j = 0; j < 2; j++) {
                    u32 BH2[2] = { bh[bt][j], bh[bt][j + 2] };
                    mma16816(acc[mt][bt * 2 + j], ah[mt], BH2);
                }
    }
}

// warp-level scan of one L/R row pair in smem -> g_S (identical math to old k_scan_w)
__device__ __forceinline__ void scan_pair(const float* smf, int p, int lane,
                                          float* __restrict__ Sdst)
{
    float4 a = *(const float4*)&smf[p * 132 + lane * 4];          // L row (reverse cummax)
    float4 r = *(const float4*)&smf[(p + 64) * 132 + lane * 4];   // R row (forward cummax)
    float p0 = r.x, p1 = fmaxf(p0, r.y), p2 = fmaxf(p1, r.z), p3 = fmaxf(p2, r.w);
    float m = p3;
#pragma unroll
    for (int o = 1; o < 32; o <<= 1) {
        float v = __shfl_up_sync(0xffffffffu, m, o);
        if (lane >= o) m = fmaxf(m, v);
    }
    float ex = __shfl_up_sync(0xffffffffu, m, 1);
    if (lane == 0) ex = -INFINITY;
    float q3 = a.w, q2 = fmaxf(q3, a.z), q1 = fmaxf(q2, a.y), q0 = fmaxf(q1, a.x);
    float mm = q0;
#pragma unroll
    for (int o = 1; o < 32; o <<= 1) {
        float v = __shfl_down_sync(0xffffffffu, mm, o);
        if (lane + o < 32) mm = fmaxf(mm, v);
    }
    float exr = __shfl_down_sync(0xffffffffu, mm, 1);
    if (lane == 31) exr = -INFINITY;
    float4 o4;
    o4.x = fmaxf(ex, p0) + fmaxf(exr, q0);
    o4.y = fmaxf(ex, p1) + fmaxf(exr, q1);
    o4.z = fmaxf(ex, p2) + fmaxf(exr, q2);
    o4.w = fmaxf(ex, p3) + fmaxf(exr, q3);
    *(float4*)(Sdst + lane * 4) = o4;
}

// ---------------- fused branch-PAIR 3x3 conv + BN + relu (+fused w-scan for bz=0) --------
// grid = (H=128, B=8, pair=2); bz=0 -> branches {L,R} (scan fused, writes g_S)
//                              bz=1 -> branches {T,B} (writes g_y[0],g_y[1])
__global__ __launch_bounds__(512, 1)
void k_conv_branch(const float* __restrict__ x,
                   const float* __restrict__ ob0, const float* __restrict__ ob1,
                   const float* __restrict__ ob2, const float* __restrict__ ob3)
{
    extern __shared__ char smem_raw[];
    u32 sb = smem_u32(smem_raw);
    const int h  = blockIdx.x;
    const int b  = blockIdx.y;
    const int bz = blockIdx.z;
    const int tid = threadIdx.x;
    const int wid = tid >> 5, lid = tid & 31;
    const int wm = wid >> 1, wn = wid & 1;
    const size_t HIOFF = 9 * 16384;                  // +1 branch in g_wA

    float acc[2][8][4];
#pragma unroll
    for (int i = 0; i < 2; i++)
#pragma unroll
        for (int j = 0; j < 8; j++)
#pragma unroll
            for (int k = 0; k < 4; k++) acc[i][j][k] = 0.f;

    BReg breg;
    ldg_B(breg, tid, x, CINC, b, 0, h - 1);          // chunk 0: kh=0, c0=0
    {   // step 0 A copy (own rows)
        size_t t0 = (size_t)(bz * 18) * 16384;
        build_A_warp(sb, OFF_A0, wm, wn, lid, g_wA + t0, 128, 0, HIOFF);
        CPA_COMMIT();
    }

    for (int ch = 0; ch < 12; ch++) {
        u32 offB = (ch & 1) ? OFF_B1 : OFF_B0;
        st_B(breg, sb, offB, tid);
        __syncthreads();                             // only CTA-wide sync per chunk
        if (ch + 1 < 12) {
            int kh2 = (ch + 1) >> 2, c02 = ((ch + 1) & 3) * 64;
            ldg_B(breg, tid, x, CINC, b, c02, h + kh2 - 1);    // drains under MMAs
        }
#pragma unroll
        for (int kw = 0; kw < 3; kw++) {
            int step = ch * 3 + kw;
            CPA_WAIT0();                             // own copies of tap `step`
            PAIR_BAR(1 + wm);                        // partner rows visible; buffer freed
            if (step + 1 < 36) {
                int s2 = step + 1, ch2 = s2 / 3, kw2 = s2 - ch2 * 3;
                int kh2 = ch2 >> 2, c02 = (ch2 & 3) * 64;
                size_t tn = (size_t)(bz * 18 + kh2 * 3 + kw2) * 16384;
                build_A_warp(sb, (s2 & 1) ? OFF_A1 : OFF_A0, wm, wn, lid,
                             g_wA + tn, 128, c02 >> 1, HIOFF);
                CPA_COMMIT();
            }
            mma_chunk(sb, (step & 1) ? OFF_A1 : OFF_A0, offB, kw, wm, wn, lid, acc);
        }
    }

    const float* obs[4] = { ob0, ob1, ob2, ob3 };

    if (bz == 0) {
        // ---- fused epilogue: relu -> smem -> w-scan -> g_S ----
        float* smf = (float*)smem_raw;               // 128 rows x 132 stride = 67.6 KB
#pragma unroll
        for (int mt = 0; mt < 2; mt++) {
            __syncthreads();                         // smem free (MMA / prev pass done)
#pragma unroll
            for (int half = 0; half < 2; half++) {
                int r = wm * 16 + half * 8 + (lid >> 2);       // 0..127 local row
                int cog = (r & 15) + ((r >> 4) << 5) + mt * 16; // == old global co
                float sh = obs[cog >> 7][cog & 127];           // branch L (=0) / R (=1)
#pragma unroll
                for (int nf = 0; nf < 8; nf++) {
                    int px = wn * 64 + nf * 8 + 2 * (lid & 3);
                    float2 v;
                    v.x = fmaxf(acc[mt][nf][half * 2 + 0] + sh, 0.f);
                    v.y = fmaxf(acc[mt][nf][half * 2 + 1] + sh, 0.f);
                    *(float2*)&smf[r * 132 + px] = v;
                }
            }
            __syncthreads();
#pragma unroll
            for (int i = 0; i < 4; i++) {
                int p = wid * 4 + i;                 // co-pair 0..63 (L row p, R row p+64)
                int co = (p & 15) + ((p >> 4) << 5) + mt * 16;  // 0..127
                scan_pair(smf, p, lid,
                          g_S + ((size_t)(b * CMID + co) * HH + h) * WW);
            }
        }
    } else {
        // ---- plain epilogue for T/B branches ----
#pragma unroll
        for (int mt = 0; mt < 2; mt++) {
            int r0 = wm * 32 + mt * 16 + (lid >> 2);
#pragma unroll
            for (int half = 0; half < 2; half++) {
                int co  = r0 + half * 8;
                int brl = co >> 7;
                int cob = co & 127;
                float sh = obs[2 + brl][cob];
                float* row = g_y[brl] + ((size_t)(b * CMID + cob) * HH + h) * WW;
#pragma unroll
                for (int nf = 0; nf < 8; nf++) {
                    int px = wn * 64 + nf * 8 + 2 * (lid & 3);
                    float2 v;
                    v.x = fmaxf(acc[mt][nf][half * 2 + 0] + sh, 0.f);
                    v.y = fmaxf(acc[mt][nf][half * 2 + 1] + sh, 0.f);
                    *(float2*)(row + px) = v;
                }
            }
        }
    }
}

// ---------------- scans along H (coalesced columns); S += revcummax(T) + cummax(B) -------
__global__ void k_scan_h()
{
    int bc = blockIdx.x;
    int w  = threadIdx.x;
    const float* yt = g_y[0] + (size_t)bc * (HH * WW) + w;
    const float* yv = g_y[1] + (size_t)bc * (HH * WW) + w;
    float* Sp = g_S + (size_t)bc * (HH * WW) + w;
    float m = -INFINITY;
    for (int hq = HH - 1; hq >= 0; --hq) { m = fmaxf(m, yt[hq * WW]); Sp[hq * WW] += m; }
    m = -INFINITY;
    for (int hq = 0; hq < HH; ++hq)      { m = fmaxf(m, yv[hq * WW]); Sp[hq * WW] += m; }
}

// ---------------- conv2 3x3 over S + 1x1 skip over x + relu -> out ----------------
// grid = (H=128, B=8, 1), 512 threads, M=256, per-warp-pair A pipeline
__device__ __forceinline__ void prefetch_A_out_warp(u32 sb, int wm, int wn, int lane, int s)
{
    u32 offA = (s & 1) ? OFF_A1 : OFF_A0;
    if (s < 18) {
        int ch = s / 3, kw = s - ch * 3;
        int kh = ch >> 1, c0 = (ch & 1) * 64;
        size_t tn = (size_t)(kh * 3 + kw) * 256 * 64;
        build_A_warp(sb, offA, wm, wn, lane, g_w2 + tn, 64, c0 >> 1, (size_t)128 * 64);
    } else {
        int c = s - 18;
        build_A_warp(sb, offA, wm, wn, lane, g_w1, 128, c * 32, (size_t)128 * 128);
    }
    CPA_COMMIT();
}

__global__ __launch_bounds__(512, 1)
void k_conv_out(const float* __restrict__ x,
                const float* __restrict__ o2v, const float* __restrict__ o1v,
                float* __restrict__ out)
{
    extern __shared__ char smem_raw[];
    u32 sb = smem_u32(smem_raw);
    const int h  = blockIdx.x;
    const int b  = blockIdx.y;
    const int tid = threadIdx.x;
    const int wid = tid >> 5, lid = tid & 31;
    const int wm = wid >> 1, wn = wid & 1;

    float acc[2][8][4];
#pragma unroll
    for (int i = 0; i < 2; i++)
#pragma unroll
        for (int j = 0; j < 8; j++)
#pragma unroll
            for (int k = 0; k < 4; k++) acc[i][j][k] = 0.f;

    BReg breg;
    ldg_B(breg, tid, g_S, CMID, b, 0, h - 1);        // phase1 chunk 0
    prefetch_A_out_warp(sb, wm, wn, lid, 0);

    // phase 1: 3x3 conv over g_S (6 chunks x 3 kw = 18 steps)
    for (int ch = 0; ch < 6; ch++) {
        u32 offB = (ch & 1) ? OFF_B1 : OFF_B0;
        st_B(breg, sb, offB, tid);
        __syncthreads();
        if (ch + 1 < 6) {
            int kh2 = (ch + 1) >> 1, c02 = ((ch + 1) & 1) * 64;
            ldg_B(breg, tid, g_S, CMID, b, c02, h + kh2 - 1);
        } else {
            ldg_B(breg, tid, x, CINC, b, 0, h);      // bridge to phase 2
        }
#pragma unroll
        for (int kw = 0; kw < 3; kw++) {
            int step = ch * 3 + kw;
            CPA_WAIT0();
            PAIR_BAR(1 + wm);
            if (step + 1 < 22) prefetch_A_out_warp(sb, wm, wn, lid, step + 1);
            mma_chunk(sb, (step & 1) ? OFF_A1 : OFF_A0, offB, kw, wm, wn, lid, acc);
        }
    }
    // phase 2: 1x1 skip over x (4 chunks, 1 step each; brow offset 1 = unshifted)
    for (int c = 0; c < 4; c++) {
        int ch = 6 + c;
        u32 offB = (ch & 1) ? OFF_B1 : OFF_B0;
        st_B(breg, sb, offB, tid);
        __syncthreads();
        if (c + 1 < 4) ldg_B(breg, tid, x, CINC, b, (c + 1) * 64, h);
        int step = 18 + c;
        CPA_WAIT0();
        PAIR_BAR(1 + wm);
        if (step + 1 < 22) prefetch_A_out_warp(sb, wm, wn, lid, step + 1);
        mma_chunk(sb, (step & 1) ? OFF_A1 : OFF_A0, offB, 1, wm, wn, lid, acc);
    }

#pragma unroll
    for (int mt = 0; mt < 2; mt++) {
        int r0 = wm * 32 + mt * 16 + (lid >> 2);
#pragma unroll
        for (int half = 0; half < 2; half++) {
            int co = r0 + half * 8;                  // 0..255
            float sh = o2v[co] + o1v[co];
            float* row = out + ((size_t)(b * COUTC + co) * HH + h) * WW;
#pragma unroll
            for (int nf = 0; nf < 8; nf++) {
                int px = wn * 64 + nf * 8 + 2 * (lid & 3);
                float2 v;
                v.x = fmaxf(acc[mt][nf][half * 2 + 0] + sh, 0.f);
                v.y = fmaxf(acc[mt][nf][half * 2 + 1] + sh, 0.f);
                *(float2*)(row + px) = v;
            }
        }
    }
}

// ---------------- launch ----------------
// NOTE: launch order puts k_conv_branch at index 5 so ncu (-s 5 -c 1) captures it.
extern "C" void kernel_launch(void* const* d_in, const int* in_sizes, int n_in,
                              void* d_out, int out_size)
{
    const float* x   = (const float*)d_in[0];
    const float* w_l = (const float*)d_in[1];
    const float* s_l = (const float*)d_in[2];
    const float* o_l = (const float*)d_in[3];
    const float* w_r = (const float*)d_in[4];
    const float* s_r = (const float*)d_in[5];
    const float* o_r = (const float*)d_in[6];
    const float* w_t = (const float*)d_in[7];
    const float* s_t = (const float*)d_in[8];
    const float* o_t = (const float*)d_in[9];
    const float* w_b = (const float*)d_in[10];
    const float* s_b = (const float*)d_in[11];
    const float* o_b = (const float*)d_in[12];
    const float* w2  = (const float*)d_in[13];
    const float* s2  = (const float*)d_in[14];
    const float* o2  = (const float*)d_in[15];
    const float* w1  = (const float*)d_in[16];
    const float* s1  = (const float*)d_in[17];
    const float* o1  = (const float*)d_in[18];
    float* out = (float*)d_out;

    cudaFuncSetAttribute(k_conv_branch, cudaFuncAttributeMaxDynamicSharedMemorySize, SMEM_BYTES);
    cudaFuncSetAttribute(k_conv_out,    cudaFuncAttributeMaxDynamicSharedMemorySize, SMEM_BYTES);

    k_repack_br<<<576, 256>>>(w_l, s_l, 0);          // 0
    k_repack_br<<<576, 256>>>(w_r, s_r, 1);          // 1
    k_repack_br<<<576, 256>>>(w_t, s_t, 2);          // 2
    k_repack_br<<<576, 256>>>(w_b, s_b, 3);          // 3
    k_repack_w2<<<576, 256>>>(w2, s2);               // 4
    dim3 g1(HH, BN, 2);
    k_conv_branch<<<g1, 512, SMEM_BYTES>>>(x, o_l, o_r, o_t, o_b);   // 5 <- ncu target
    k_repack_w1<<<128, 256>>>(w1, s1);               // 6 (needed only by conv_out)
    k_scan_h<<<BN * CMID, 128>>>();
    dim3 g3(HH, BN, 1);
    k_conv_out<<<g3, 512, SMEM_BYTES>>>(x, o2, o1, out);
}

// round 16
// speedup vs baseline: 2.5160x; 1.0135x over previous
#include <cuda_runtime.h>
#include <cuda_fp16.h>
#include <cstdint>
#include <math.h>

#define BN    8
#define CINC  256
#define CMID  128
#define COUTC 256
#define HH    128
#define WW    128
#define HWSZ  16384

typedef uint32_t u32;

// ---------------- scratch (static __device__ — allocation-free) ----------------
__device__ __half g_yh[4][BN * CMID * HH * WW];  // branch conv outputs (post-relu, fp16)
__device__ float  g_S[BN * CMID * HH * WW];      // scanned sum (fp32)
// fp16 weights (single plane): branch [tap=br*9+kh*3+kw][co=128][cipair=128]
__device__ __align__(16) __half2 g_wA[36 * 128 * 128];
__device__ __align__(16) __half2 g_w2[9 * 256 * 64];   // [t][co=256][cipair=64]
__device__ __align__(16) __half2 g_w1[256 * 128];      // [co=256][cipair=128]

// ---------------- helpers ----------------
__device__ __forceinline__ u32 smem_u32(const void* p) {
    u32 a;
    asm("{ .reg .u64 t; cvta.to.shared.u64 t, %1; cvt.u32.u64 %0, t; }" : "=r"(a) : "l"(p));
    return a;
}

// XOR swizzle: byte bits [6:4] ^= bits [9:7]  (rows are 128B)
#define SWZ(off) ((off) ^ (((off) >> 3) & 0x70))

__device__ __forceinline__ void ldm_x4(u32* r, u32 addr) {
    asm volatile("ldmatrix.sync.aligned.m8n8.x4.shared.b16 {%0,%1,%2,%3}, [%4];"
                 : "=r"(r[0]), "=r"(r[1]), "=r"(r[2]), "=r"(r[3]) : "r"(addr));
}
__device__ __forceinline__ void mma16816(float* d, const u32* a, const u32* b) {
    asm volatile("mma.sync.aligned.m16n8k16.row.col.f32.f16.f16.f32 "
                 "{%0,%1,%2,%3}, {%4,%5,%6,%7}, {%8,%9}, {%0,%1,%2,%3};"
                 : "+f"(d[0]), "+f"(d[1]), "+f"(d[2]), "+f"(d[3])
                 : "r"(a[0]), "r"(a[1]), "r"(a[2]), "r"(a[3]), "r"(b[0]), "r"(b[1]));
}
__device__ __forceinline__ void cpa16(u32 d, const void* s) {
    asm volatile("cp.async.cg.shared.global [%0], [%1], 16;" :: "r"(d), "l"(s));
}
#define CPA_COMMIT() asm volatile("cp.async.commit_group;" ::: "memory")
#define CPA_WAIT0()  asm volatile("cp.async.wait_group 0;" ::: "memory")
#define PAIR_BAR(id) asm volatile("bar.sync %0, 64;" :: "r"(id) : "memory")

// smem (per CTA, sized for 2 CTAs/SM): two A buffers (128 rows) + two B buffers (132 rows)
#define BSZ    16896                    // 132 * 128 bytes
#define OFF_A0 0
#define OFF_A1 16384
#define OFF_B0 32768
#define OFF_B1 (32768 + BSZ)            // 49664
#define SMEM_BYTES (OFF_B1 + BSZ)       // 66560

// pack two fp32 -> fp16x2 word and store to smem
__device__ __forceinline__ void stpack(float v0, float v1, u32 addr) {
    __half h0 = __float2half(v0), h1 = __float2half(v1);
    u32 hv;
    asm("mov.b32 %0, {%1, %2};" : "=r"(hv) : "h"(*(unsigned short*)&h0), "h"(*(unsigned short*)&h1));
    asm volatile("st.shared.b32 [%0], %1;" :: "r"(addr), "r"(hv) : "memory");
}

// ---------------- weight repack (+BN scale fold, fp16) ----------------
__global__ void k_repack_br(const float* __restrict__ w, const float* __restrict__ s, int br)
{
    int slot = blockIdx.x * 256 + threadIdx.x;       // 9*128*128
    if (slot >= 147456) return;
    int pair = slot & 127;
    int co   = (slot >> 7) & 127;
    int t    = slot >> 14;
    int kh = t / 3, kw = t % 3;
    int ci = pair * 2;
    float sc = s[co];
    float v0 = w[((co * CINC + ci)     * 3 + kh) * 3 + kw] * sc;
    float v1 = w[((co * CINC + ci + 1) * 3 + kh) * 3 + kw] * sc;
    g_wA[((br * 9 + t) * 128 + co) * 128 + pair] =
        __halves2half2(__float2half(v0), __float2half(v1));
}

__global__ void k_repack_w2(const float* __restrict__ w, const float* __restrict__ s)
{
    int slot = blockIdx.x * 256 + threadIdx.x;       // 9*256*64
    if (slot >= 147456) return;
    int pair = slot & 63;
    int co   = (slot >> 6) & 255;
    int t    = slot >> 14;
    int kh = t / 3, kw = t % 3;
    int ci = pair * 2;
    float sc = s[co];
    float v0 = w[((co * CMID + ci)     * 3 + kh) * 3 + kw] * sc;
    float v1 = w[((co * CMID + ci + 1) * 3 + kh) * 3 + kw] * sc;
    g_w2[(t * 256 + co) * 64 + pair] =
        __halves2half2(__float2half(v0), __float2half(v1));
}

__global__ void k_repack_w1(const float* __restrict__ w, const float* __restrict__ s)
{
    int slot = blockIdx.x * 256 + threadIdx.x;       // 256*128
    if (slot >= 32768) return;
    int pair = slot & 127;
    int co   = slot >> 7;
    int ci = pair * 2;
    float sc = s[co];
    float v0 = w[co * CINC + ci]     * sc;
    float v1 = w[co * CINC + ci + 1] * sc;
    g_w1[co * 128 + pair] =
        __halves2half2(__float2half(v0), __float2half(v1));
}

// ---------------- per-warp A copy: 16 rows x 128B (8 warps cover M=128) ----------------
__device__ __forceinline__ void build_A_warp(u32 sb, u32 offA, int wm, int wn, int lane,
                                             const __half2* __restrict__ wsrc,
                                             int rsp, int pair0)
{
#pragma unroll
    for (int q = 0; q < 4; q++) {
        int slot = lane + 32 * q;            // 0..127
        int co = wm * 32 + wn * 16 + (slot >> 3);   // 0..127
        int c  = slot & 7;
        u32 d = SWZ((u32)(co * 128 + c * 16));
        cpa16(sb + offA + d, (const char*)(wsrc + (size_t)co * rsp + pair0) + c * 16);
    }
}

// ---------------- direct B build: fp32 src -> fp16 swizzled tile (132 rows) ----------------
__device__ __forceinline__ void build_B_direct(u32 sb, u32 offB, int tid,
                                               const float* __restrict__ src,
                                               int nchan, int b, int c0, int srow)
{
    const size_t HW = (size_t)HWSZ;
    bool rowok = (srow >= 0) && (srow < HH);
    const float* base = src + ((size_t)(b * nchan + c0) * HH + (rowok ? srow : 0)) * WW;
    int p  = tid & 127;
    int gp = tid >> 7;                       // 0..1
    int spx = p - 1;
    bool okm = rowok && (spx >= 0);
    const float* bp = base + spx;
#pragma unroll
    for (int q = 0; q < 16; q++) {
        int cil = gp * 32 + 2 * q;
        float v0 = okm ? bp[(size_t)cil * HW] : 0.f;
        float v1 = okm ? bp[(size_t)(cil + 1) * HW] : 0.f;
        stpack(v0, v1, sb + offB + SWZ((u32)(p * 128 + 2 * cil)));
    }
    if (tid < 128) {                         // tail rows 128..131 (src px 127..130)
        int rr = 128 + (tid >> 5);
        int pc = tid & 31;
        int sp2 = rr - 1;
        bool ok = rowok && (sp2 < WW);
        float v0 = ok ? base[(size_t)(2 * pc) * HW + sp2] : 0.f;
        float v1 = ok ? base[(size_t)(2 * pc + 1) * HW + sp2] : 0.f;
        stpack(v0, v1, sb + offB + SWZ((u32)(rr * 128 + 4 * pc)));
    }
}

// ---------------- mma over one 64-k chunk; M=128, warp = 32co x 64px ----------------
// 8 warps: wm = wid>>1 (0..3), wn = wid&1 (0..1)
__device__ __forceinline__ void mma_chunk(u32 sb, u32 offA, u32 offB, int kw,
                                          int wm, int wn, int lid, float acc[2][8][4])
{
    const u32 lrow  = (u32)(lid & 15) * 128;
    const u32 lkh   = (u32)((lid >> 4) << 4);
    const u32 brow0 = (u32)kw * 128 + lrow;
#pragma unroll
    for (int ks = 0; ks < 4; ks++) {
        const u32 kb = (u32)(ks * 32) + lkh;
        u32 ah[2][4], bh[4][4];
#pragma unroll
        for (int mt = 0; mt < 2; mt++) {
            u32 off = SWZ((u32)((wm * 32 + mt * 16) * 128) + lrow + kb);
            ldm_x4(ah[mt], sb + offA + off);
        }
#pragma unroll
        for (int bt = 0; bt < 4; bt++) {
            u32 off = SWZ((u32)((wn * 64 + bt * 16) * 128) + brow0 + kb);
            ldm_x4(bh[bt], sb + offB + off);
        }
#pragma unroll
        for (int mt = 0; mt < 2; mt++)
#pragma unroll
            for (int bt = 0; bt < 4; bt++)
#pragma unroll
                for (int j = 0; j < 2; j++) {
                    u32 BH2[2] = { bh[bt][j], bh[bt][j + 2] };
                    mma16816(acc[mt][bt * 2 + j], ah[mt], BH2);
                }
    }
}

// ---------------- 3x3 branch conv + BN + relu -> g_yh[br] (fp16) ----------------
// grid = (H=128, B=8, br=4), 256 threads, 2 CTAs/SM
__global__ __launch_bounds__(256, 2)
void k_conv_branch(const float* __restrict__ x,
                   const float* __restrict__ ob0, const float* __restrict__ ob1,
                   const float* __restrict__ ob2, const float* __restrict__ ob3)
{
    extern __shared__ char smem_raw[];
    u32 sb = smem_u32(smem_raw);
    const int h  = blockIdx.x;
    const int b  = blockIdx.y;
    const int br = blockIdx.z;
    const int tid = threadIdx.x;
    const int wid = tid >> 5, lid = tid & 31;
    const int wm = wid >> 1, wn = wid & 1;

    float acc[2][8][4];
#pragma unroll
    for (int i = 0; i < 2; i++)
#pragma unroll
        for (int j = 0; j < 8; j++)
#pragma unroll
            for (int k = 0; k < 4; k++) acc[i][j][k] = 0.f;

    build_A_warp(sb, OFF_A0, wm, wn, lid, g_wA + (size_t)(br * 9) * 16384, 128, 0);
    CPA_COMMIT();

    for (int ch = 0; ch < 12; ch++) {
        int kh = ch >> 2, c0 = (ch & 3) * 64;
        u32 offB = (ch & 1) ? OFF_B1 : OFF_B0;
        build_B_direct(sb, offB, tid, x, CINC, b, c0, h + kh - 1);
        __syncthreads();
#pragma unroll
        for (int kw = 0; kw < 3; kw++) {
            int step = ch * 3 + kw;
            CPA_WAIT0();
            PAIR_BAR(1 + wm);
            if (step + 1 < 36) {
                int s2 = step + 1, ch2 = s2 / 3, kw2 = s2 - ch2 * 3;
                int kh2 = ch2 >> 2, c02 = (ch2 & 3) * 64;
                build_A_warp(sb, (s2 & 1) ? OFF_A1 : OFF_A0, wm, wn, lid,
                             g_wA + (size_t)(br * 9 + kh2 * 3 + kw2) * 16384, 128, c02 >> 1);
                CPA_COMMIT();
            }
            mma_chunk(sb, (step & 1) ? OFF_A1 : OFF_A0, offB, kw, wm, wn, lid, acc);
        }
    }

    const float* ob = (br == 0) ? ob0 : (br == 1) ? ob1 : (br == 2) ? ob2 : ob3;
    __half* yb = g_yh[br];
#pragma unroll
    for (int mt = 0; mt < 2; mt++) {
#pragma unroll
        for (int half = 0; half < 2; half++) {
            int co = wm * 32 + mt * 16 + half * 8 + (lid >> 2);   // 0..127
            float sh = ob[co];
            __half* row = yb + ((size_t)(b * CMID + co) * HH + h) * WW;
#pragma unroll
            for (int nf = 0; nf < 8; nf++) {
                int px = wn * 64 + nf * 8 + 2 * (lid & 3);
                float2 v;
                v.x = fmaxf(acc[mt][nf][half * 2 + 0] + sh, 0.f);
                v.y = fmaxf(acc[mt][nf][half * 2 + 1] + sh, 0.f);
                *(__half2*)(row + px) = __float22half2_rn(v);
            }
        }
    }
}

// ---------------- scan along W: S = revcummax(yL) + cummax(yR) ----------------
__global__ void k_scan_w()
{
    int bc   = blockIdx.x;
    int wq   = threadIdx.x >> 5;
    int lane = threadIdx.x & 31;
    const size_t plane = (size_t)bc * HWSZ;
    for (int hr = wq; hr < HH; hr += 16) {
        const __half2* yl2 = (const __half2*)(g_yh[0] + plane + (size_t)hr * WW);
        const __half2* yr2 = (const __half2*)(g_yh[1] + plane + (size_t)hr * WW);
        __half2 a01 = yl2[lane * 2], a23 = yl2[lane * 2 + 1];
        __half2 r01 = yr2[lane * 2], r23 = yr2[lane * 2 + 1];
        float ax = __low2float(a01), ay = __high2float(a01);
        float az = __low2float(a23), aw = __high2float(a23);
        float rx = __low2float(r01), ry = __high2float(r01);
        float rz = __low2float(r23), rw = __high2float(r23);
        float p0 = rx, p1 = fmaxf(p0, ry), p2 = fmaxf(p1, rz), p3 = fmaxf(p2, rw);
        float m = p3;
#pragma unroll
        for (int o = 1; o < 32; o <<= 1) {
            float v = __shfl_up_sync(0xffffffffu, m, o);
            if (lane >= o) m = fmaxf(m, v);
        }
        float ex = __shfl_up_sync(0xffffffffu, m, 1);
        if (lane == 0) ex = -INFINITY;
        float q3 = aw, q2 = fmaxf(q3, az), q1 = fmaxf(q2, ay), q0 = fmaxf(q1, ax);
        float mm = q0;
#pragma unroll
        for (int o = 1; o < 32; o <<= 1) {
            float v = __shfl_down_sync(0xffffffffu, mm, o);
            if (lane + o < 32) mm = fmaxf(mm, v);
        }
        float exr = __shfl_down_sync(0xffffffffu, mm, 1);
        if (lane == 31) exr = -INFINITY;
        float4 o4;
        o4.x = fmaxf(ex, p0) + fmaxf(exr, q0);
        o4.y = fmaxf(ex, p1) + fmaxf(exr, q1);
        o4.z = fmaxf(ex, p2) + fmaxf(exr, q2);
        o4.w = fmaxf(ex, p3) + fmaxf(exr, q3);
        ((float4*)(g_S + plane + (size_t)hr * WW))[lane] = o4;
    }
}

// ---------------- scan along H: S += revcummax(yT) + cummax(yB) ----------------
__global__ void k_scan_h()
{
    int bc = blockIdx.x;
    int w  = threadIdx.x;
    const __half* yt = g_yh[2] + (size_t)bc * HWSZ + w;
    const __half* yv = g_yh[3] + (size_t)bc * HWSZ + w;
    float* Sp = g_S + (size_t)bc * HWSZ + w;
    float m = -INFINITY;
    for (int hq = HH - 1; hq >= 0; --hq) {
        m = fmaxf(m, __half2float(yt[hq * WW])); Sp[hq * WW] += m;
    }
    m = -INFINITY;
    for (int hq = 0; hq < HH; ++hq) {
        m = fmaxf(m, __half2float(yv[hq * WW])); Sp[hq * WW] += m;
    }
}

// ---------------- conv2 3x3 over S + 1x1 skip over x + relu -> out ----------------
// grid = (H=128, B=8, ct=2), 256 threads, 2 CTAs/SM
__device__ __forceinline__ void prefetch_A_out_warp(u32 sb, int wm, int wn, int lane,
                                                    int ct, int s)
{
    u32 offA = (s & 1) ? OFF_A1 : OFF_A0;
    if (s < 18) {
        int ch = s / 3, kw = s - ch * 3;
        int kh = ch >> 1, c0 = (ch & 1) * 64;
        build_A_warp(sb, offA, wm, wn, lane,
                     g_w2 + ((size_t)(kh * 3 + kw) * 256 + ct * 128) * 64, 64, c0 >> 1);
    } else {
        int c = s - 18;
        build_A_warp(sb, offA, wm, wn, lane,
                     g_w1 + (size_t)ct * 128 * 128, 128, c * 32);
    }
    CPA_COMMIT();
}

__global__ __launch_bounds__(256, 2)
void k_conv_out(const float* __restrict__ x,
                const float* __restrict__ o2v, const float* __restrict__ o1v,
                float* __restrict__ out)
{
    extern __shared__ char smem_raw[];
    u32 sb = smem_u32(smem_raw);
    const int h  = blockIdx.x;
    const int b  = blockIdx.y;
    const int ct = blockIdx.z;
    const int tid = threadIdx.x;
    const int wid = tid >> 5, lid = tid & 31;
    const int wm = wid >> 1, wn = wid & 1;

    float acc[2][8][4];
#pragma unroll
    for (int i = 0; i < 2; i++)
#pragma unroll
        for (int j = 0; j < 8; j++)
#pragma unroll
            for (int k = 0; k < 4; k++) acc[i][j][k] = 0.f;

    prefetch_A_out_warp(sb, wm, wn, lid, ct, 0);

    // phase 1: 3x3 conv over g_S (6 chunks x 3 kw = 18 steps)
    for (int ch = 0; ch < 6; ch++) {
        int kh = ch >> 1, c0 = (ch & 1) * 64;
        u32 offB = (ch & 1) ? OFF_B1 : OFF_B0;
        build_B_direct(sb, offB, tid, g_S, CMID, b, c0, h + kh - 1);
        __syncthreads();
#pragma unroll
        for (int kw = 0; kw < 3; kw++) {
            int step = ch * 3 + kw;
            CPA_WAIT0();
            PAIR_BAR(1 + wm);
            if (step + 1 < 22) prefetch_A_out_warp(sb, wm, wn, lid, ct, step + 1);
            mma_chunk(sb, (step & 1) ? OFF_A1 : OFF_A0, offB, kw, wm, wn, lid, acc);
        }
    }
    // phase 2: 1x1 skip over x (4 chunks; brow offset 1 = unshifted pixels)
    for (int c = 0; c < 4; c++) {
        int ch = 6 + c;
        u32 offB = (ch & 1) ? OFF_B1 : OFF_B0;
        build_B_direct(sb, offB, tid, x, CINC, b, c * 64, h);
        __syncthreads();
        int step = 18 + c;
        CPA_WAIT0();
        PAIR_BAR(1 + wm);
        if (step + 1 < 22) prefetch_A_out_warp(sb, wm, wn, lid, ct, step + 1);
        mma_chunk(sb, (step & 1) ? OFF_A1 : OFF_A0, offB, 1, wm, wn, lid, acc);
    }

#pragma unroll
    for (int mt = 0; mt < 2; mt++) {
#pragma unroll
        for (int half = 0; half < 2; half++) {
            int co = ct * 128 + wm * 32 + mt * 16 + half * 8 + (lid >> 2);
            float sh = o2v[co] + o1v[co];
            float* row = out + ((size_t)(b * COUTC + co) * HH + h) * WW;
#pragma unroll
            for (int nf = 0; nf < 8; nf++) {
                int px = wn * 64 + nf * 8 + 2 * (lid & 3);
                float2 v;
                v.x = fmaxf(acc[mt][nf][half * 2 + 0] + sh, 0.f);
                v.y = fmaxf(acc[mt][nf][half * 2 + 1] + sh, 0.f);
                *(float2*)(row + px) = v;
            }
        }
    }
}

// ---------------- launch ----------------
extern "C" void kernel_launch(void* const* d_in, const int* in_sizes, int n_in,
                              void* d_out, int out_size)
{
    const float* x   = (const float*)d_in[0];
    const float* w_l = (const float*)d_in[1];
    const float* s_l = (const float*)d_in[2];
    const float* o_l = (const float*)d_in[3];
    const float* w_r = (const float*)d_in[4];
    const float* s_r = (const float*)d_in[5];
    const float* o_r = (const float*)d_in[6];
    const float* w_t = (const float*)d_in[7];
    const float* s_t = (const float*)d_in[8];
    const float* o_t = (const float*)d_in[9];
    const float* w_b = (const float*)d_in[10];
    const float* s_b = (const float*)d_in[11];
    const float* o_b = (const float*)d_in[12];
    const float* w2  = (const float*)d_in[13];
    const float* s2  = (const float*)d_in[14];
    const float* o2  = (const float*)d_in[15];
    const float* w1  = (const float*)d_in[16];
    const float* s1  = (const float*)d_in[17];
    const float* o1  = (const float*)d_in[18];
    float* out = (float*)d_out;

    cudaFuncSetAttribute(k_conv_branch, cudaFuncAttributeMaxDynamicSharedMemorySize, SMEM_BYTES);
    cudaFuncSetAttribute(k_conv_out,    cudaFuncAttributeMaxDynamicSharedMemorySize, SMEM_BYTES);

    k_repack_br<<<576, 256>>>(w_l, s_l, 0);
    k_repack_br<<<576, 256>>>(w_r, s_r, 1);
    k_repack_br<<<576, 256>>>(w_t, s_t, 2);
    k_repack_br<<<576, 256>>>(w_b, s_b, 3);
    k_repack_w2<<<576, 256>>>(w2, s2);
    dim3 g1(HH, BN, 4);
    k_conv_branch<<<g1, 256, SMEM_BYTES>>>(x, o_l, o_r, o_t, o_b);
    k_repack_w1<<<128, 256>>>(w1, s1);
    k_scan_w<<<BN * CMID, 512>>>();
    k_scan_h<<<BN * CMID, 128>>>();
    dim3 g3(HH, BN, 2);
    k_conv_out<<<g3, 256, SMEM_BYTES>>>(x, o2, o1, out);
}